// round 4
// baseline (speedup 1.0000x reference)
#include <cuda_runtime.h>
#include <math.h>
#include <string.h>
#include <stdint.h>

#define NND   4096
#define KNBR  9
#define INC   32
#define OUTC  64
#define HID   128
#define SDIM  4096   // HID * INC
#define KSPL  2
#define KLEN  (SDIM / KSPL)
#define KC    32

// ---------------- scratch (static device globals; no allocation) ----------------
__device__ int   g_idx[2][NND * KNBR];
__device__ float g_pd[2][4][NND][KNBR];               // partial knn distances
__device__ int   g_pi[2][4][NND][KNBR];               // partial knn indices
__device__ float g_S[2][(size_t)NND * SDIM];          // 2 x 64 MB
__device__ float g_xjm[2][NND * INC];
__device__ float g_part[2 * KSPL * NND * OUTC];       // (br, kz) GEMM partials

// Order matches jax.lax.top_k(-d): ascending d, ties -> ascending index.
__device__ __forceinline__ bool knn_less(float d, int i, float d2, int i2) {
    return (d < d2) || (d == d2 && i < i2);
}

__device__ __forceinline__ void knn_insert(float dist, int j, float bd[KNBR], int bi[KNBR]) {
    if (knn_less(dist, j, bd[KNBR - 1], bi[KNBR - 1])) {
        float cd = dist; int ci = j;
#pragma unroll
        for (int r = 0; r < KNBR; r++) {
            bool sw = knn_less(cd, ci, bd[r], bi[r]);
            float td = bd[r]; int ti = bi[r];
            if (sw) { bd[r] = cd; bi[r] = ci; cd = td; ci = ti; }
        }
    }
}

// Warp-wide 9-round merge of per-lane sorted lists; writes (d, i) pairs.
__device__ __forceinline__ void knn_merge_warp(float* md, int* mi, const float bd[KNBR],
                                               const int bi[KNBR], int lane,
                                               float* opd, int* opi, int q) {
#pragma unroll
    for (int r = 0; r < KNBR; r++) { md[lane * KNBR + r] = bd[r]; mi[lane * KNBR + r] = bi[r]; }
    __syncwarp();
    int p = 0;
    for (int r = 0; r < KNBR; r++) {
        float cd = (p < KNBR) ? md[lane * KNBR + p] : 3.4e38f;
        int   ci = (p < KNBR) ? mi[lane * KNBR + p] : 0x7FFFFFFF;
        float rd = cd; int ri = ci;
#pragma unroll
        for (int off = 16; off; off >>= 1) {
            float od = __shfl_xor_sync(0xFFFFFFFFu, rd, off);
            int   oi = __shfl_xor_sync(0xFFFFFFFFu, ri, off);
            if (knn_less(od, oi, rd, ri)) { rd = od; ri = oi; }
        }
        if (ci == ri && p < KNBR) p++;   // candidate indices unique per lane
        if (lane == 0) { opd[q * KNBR + r] = rd; opi[q * KNBR + r] = ri; }
    }
    __syncwarp();
}

// ---------------- 1) KNN on pos: 2 candidate parts, part's pos slice in smem ---
#define PPART (NND / 2)
__global__ __launch_bounds__(256) void knn_pos_kernel(const float* __restrict__ pos) {
    __shared__ float smem[PPART * 3];   // 24 KB; merge overlay after
    int t = threadIdx.x, w = t >> 5, lane = t & 31;
    int q = blockIdx.x * 8 + w;
    int part = blockIdx.y;
    int base = part * PPART;

    for (int v = t; v < PPART * 3; v += 256) smem[v] = pos[base * 3 + v];
    __syncthreads();

    float q0 = pos[q * 3 + 0], q1 = pos[q * 3 + 1], q2 = pos[q * 3 + 2];
    float sqq = 0.f;
    sqq = fmaf(q0, q0, sqq); sqq = fmaf(q1, q1, sqq); sqq = fmaf(q2, q2, sqq);

    float bd[KNBR]; int bi[KNBR];
#pragma unroll
    for (int r = 0; r < KNBR; r++) { bd[r] = 3.4e38f; bi[r] = 0x7FFFFFFF; }

    for (int jl = lane; jl < PPART; jl += 32) {
        float c0 = smem[jl * 3 + 0], c1 = smem[jl * 3 + 1], c2 = smem[jl * 3 + 2];
        float acc = 0.f;
        acc = fmaf(q0, c0, acc); acc = fmaf(q1, c1, acc); acc = fmaf(q2, c2, acc);
        float sqj = 0.f;
        sqj = fmaf(c0, c0, sqj); sqj = fmaf(c1, c1, sqj); sqj = fmaf(c2, c2, sqj);
        float dist = (sqq + sqj) - 2.0f * acc;
        knn_insert(dist, base + jl, bd, bi);
    }
    __syncthreads();   // done reading smem; overlay merge buffers

    float* md = smem + (size_t)w * 288;
    int*   mi = (int*)(smem + 8 * 288) + (size_t)w * 288;
    knn_merge_warp(md, mi, bd, bi, lane, &g_pd[0][part][0][0], &g_pi[0][part][0][0], q);
}

// ---------------- 2) KNN on x: 4 candidate parts, tiled smem, 2 queries/warp ---
#define TS 256
#define FPART (NND / 4)
__global__ __launch_bounds__(256) void knn_feat_kernel(const float* __restrict__ x) {
    __shared__ float s_tile[TS * 33];   // stride-33 pad: conflict-free
    __shared__ float s_sq[TS];
    int t = threadIdx.x, w = t >> 5, lane = t & 31;
    int qa_i = blockIdx.x * 16 + w * 2;
    int qb_i = qa_i + 1;
    int part = blockIdx.y;
    int base0 = part * FPART;

    float qa[INC], qb[INC];
#pragma unroll
    for (int d = 0; d < INC; d++) qa[d] = x[qa_i * INC + d];
#pragma unroll
    for (int d = 0; d < INC; d++) qb[d] = x[qb_i * INC + d];
    float sqa = 0.f, sqb = 0.f;
#pragma unroll
    for (int d = 0; d < INC; d++) sqa = fmaf(qa[d], qa[d], sqa);
#pragma unroll
    for (int d = 0; d < INC; d++) sqb = fmaf(qb[d], qb[d], sqb);

    float bda[KNBR], bdb[KNBR]; int bia[KNBR], bib[KNBR];
#pragma unroll
    for (int r = 0; r < KNBR; r++) {
        bda[r] = 3.4e38f; bia[r] = 0x7FFFFFFF;
        bdb[r] = 3.4e38f; bib[r] = 0x7FFFFFFF;
    }

    for (int base = base0; base < base0 + FPART; base += TS) {
        __syncthreads();
#pragma unroll
        for (int v = t; v < TS * INC; v += 256) {
            int r = v >> 5, d = v & 31;
            s_tile[r * 33 + d] = x[(size_t)(base + r) * INC + d];
        }
        __syncthreads();
        {   // per-row sq with identical fmaf chain (thread t owns row t)
            float s = 0.f;
#pragma unroll
            for (int d = 0; d < INC; d++) { float v = s_tile[t * 33 + d]; s = fmaf(v, v, s); }
            s_sq[t] = s;
        }
        __syncthreads();

        for (int s = 0; s < TS; s += 32) {
            int r = s + lane;
            int j = base + r;
            const float* c = &s_tile[r * 33];
            float acc0 = 0.f, acc1 = 0.f;
#pragma unroll
            for (int d = 0; d < INC; d++) {
                float cv = c[d];
                acc0 = fmaf(qa[d], cv, acc0);
                acc1 = fmaf(qb[d], cv, acc1);
            }
            float sqj = s_sq[r];
            knn_insert((sqa + sqj) - 2.0f * acc0, j, bda, bia);
            knn_insert((sqb + sqj) - 2.0f * acc1, j, bdb, bib);
        }
    }
    __syncthreads();   // done with s_tile; overlay merge buffers

    float* md = s_tile + (size_t)w * 288;
    int*   mi = (int*)(s_tile + 8 * 288) + (size_t)w * 288;
    knn_merge_warp(md, mi, bda, bia, lane, &g_pd[1][part][0][0], &g_pi[1][part][0][0], qa_i);
    knn_merge_warp(md, mi, bdb, bib, lane, &g_pd[1][part][0][0], &g_pi[1][part][0][0], qb_i);
}

// ---------------- 3) exact P-way merge of per-part top-9 lists -----------------
__global__ __launch_bounds__(256) void knn_mergeP_kernel() {
    int idx = blockIdx.x * 256 + threadIdx.x;   // 8192
    int br = idx >> 12, q = idx & (NND - 1);
    int P = br ? 4 : 2;
    int p[4] = {0, 0, 0, 0};
    for (int r = 0; r < KNBR; r++) {
        float bd = 3.4e38f; int bi = 0x7FFFFFFF, bt = 0;
        for (int t = 0; t < P; t++) {
            float d = g_pd[br][t][q][p[t]];
            int   i = g_pi[br][t][q][p[t]];
            if (knn_less(d, i, bd, bi)) { bd = d; bi = i; bt = t; }
        }
        p[bt]++;
        g_idx[br][q * KNBR + r] = bi;
    }
}

// ---------------- 4) per-(node, branch): attrs -> h -> S, xjmean ---------------
__global__ __launch_bounds__(128) void buildS_kernel(
    const float* __restrict__ x, const float* __restrict__ pos,
    const float* __restrict__ w1g, const float* __restrict__ b1g,
    const float* __restrict__ w1f, const float* __restrict__ b1f) {
    int n = blockIdx.x, br = blockIdx.y;
    int t = threadIdx.x;  // 128

    __shared__ int   s_idx[KNBR];
    __shared__ float s_xj[KNBR][INC];
    __shared__ float s_attr[KNBR][3];
    __shared__ float s_h[KNBR][HID];
    __shared__ float s_pn[3];

    const int* idx = g_idx[br];
    const float* w1 = br ? w1f : w1g;
    const float* b1 = br ? b1f : b1g;

    if (t < KNBR) s_idx[t] = idx[n * KNBR + t];
    if (t < 3)    s_pn[t] = pos[n * 3 + t];
    __syncthreads();

    for (int v = t; v < KNBR * INC; v += 128)
        s_xj[v / INC][v % INC] = x[(size_t)s_idx[v / INC] * INC + (v % INC)];

    if (t < KNBR) {
        int sj = s_idx[t];
        float cx = pos[sj * 3 + 0] - s_pn[0];
        float cy = pos[sj * 3 + 1] - s_pn[1];
        float cz = pos[sj * 3 + 2] - s_pn[2];
        float rho = sqrtf((cx * cx + cy * cy) + cz * cz);
        float th  = atan2f(cy, cx);
        float ratio = cz / fmaxf(rho, 1e-12f);
        ratio = fminf(1.0f, fmaxf(-1.0f, ratio));
        float ph = acosf(ratio);
        s_attr[t][0] = rho; s_attr[t][1] = th; s_attr[t][2] = ph;
    }
    __syncthreads();

    {   // fnet layer 1 + tanh: thread t owns channel c = t
        int c = t;
        float wa = w1[c], wb = w1[HID + c], wc = w1[2 * HID + c], bb = b1[c];
        float hk[KNBR];
#pragma unroll
        for (int k = 0; k < KNBR; k++)
            hk[k] = tanhf(bb + s_attr[k][0] * wa + s_attr[k][1] * wb + s_attr[k][2] * wc);
#pragma unroll
        for (int k = 0; k < KNBR; k++) s_h[k][c] = hk[k];
    }
    __syncthreads();

    // S[c][i] = sum_k h[k][c] * xj[k][i]; coalesced writes (lane = i)
    int w = t >> 5, lane = t & 31;
    float* Sout = g_S[br] + (size_t)n * SDIM;
    for (int j = 0; j < 32; j++) {
        int c = w * 32 + j;
        float s = 0.f;
#pragma unroll
        for (int k = 0; k < KNBR; k++) s = fmaf(s_h[k][c], s_xj[k][lane], s);
        Sout[c * INC + lane] = s;
    }
    if (t < INC) {
        float m = 0.f;
#pragma unroll
        for (int k = 0; k < KNBR; k++) m += s_xj[k][t];
        g_xjm[br][n * INC + t] = m * (1.0f / 9.0f);
    }
}

// ---------------- 5) GEMM with packed f32x2 FMA + split-K ----------------------
__device__ __forceinline__ void ffma2(unsigned long long& d, unsigned long long a,
                                      unsigned long long b) {
    asm("fma.rn.f32x2 %0, %1, %2, %0;" : "+l"(d) : "l"(a), "l"(b));
}
__device__ __forceinline__ unsigned long long dup2(float v) {
    float2 t = make_float2(v, v);
    unsigned long long r;
    memcpy(&r, &t, 8);
    return r;
}

__global__ __launch_bounds__(256) void gemm_kernel(
    const float* __restrict__ w2g, const float* __restrict__ w2f) {
    __shared__ unsigned long long As2[2][KC][34];  // [k][node] pre-duplicated {v,v}
    __shared__ float Bs[2][KC][64];

    int tid = threadIdx.x;
    int tx = tid & 15, ty = tid >> 4;       // tx: out-quad, ty: node-pair
    int br = blockIdx.y, kz = blockIdx.z;
    int n0 = blockIdx.x * 32;
    const float* Sb = g_S[br] + (size_t)n0 * SDIM + (size_t)kz * KLEN;
    const float* W  = (br ? w2f : w2g) + (size_t)kz * KLEN * 64;

    int anode = tid >> 3;                   // 0..31
    int akq   = (tid & 7) * 4;              // 0..28
    int bk    = tid >> 3;                   // 0..31
    int bo    = (tid & 7) * 8;

    unsigned long long acc[2][2] = {{0ull, 0ull}, {0ull, 0ull}};

    // prologue: chunk 0 -> regs -> buf 0
    float4 aReg = *reinterpret_cast<const float4*>(&Sb[(size_t)anode * SDIM + akq]);
    float4 bR0  = *reinterpret_cast<const float4*>(&W[(size_t)bk * 64 + bo]);
    float4 bR1  = *reinterpret_cast<const float4*>(&W[(size_t)bk * 64 + bo + 4]);
    As2[0][akq + 0][anode] = dup2(aReg.x); As2[0][akq + 1][anode] = dup2(aReg.y);
    As2[0][akq + 2][anode] = dup2(aReg.z); As2[0][akq + 3][anode] = dup2(aReg.w);
    *reinterpret_cast<float4*>(&Bs[0][bk][bo])     = bR0;
    *reinterpret_cast<float4*>(&Bs[0][bk][bo + 4]) = bR1;

    int p = 0;
    const int NCH = KLEN / KC;              // 64
    for (int c = 0; c < NCH; c++) {
        __syncthreads();
        if (c + 1 < NCH) {
            int k0 = (c + 1) * KC;
            aReg = *reinterpret_cast<const float4*>(&Sb[(size_t)anode * SDIM + k0 + akq]);
            bR0  = *reinterpret_cast<const float4*>(&W[(size_t)(k0 + bk) * 64 + bo]);
            bR1  = *reinterpret_cast<const float4*>(&W[(size_t)(k0 + bk) * 64 + bo + 4]);
        }
#pragma unroll
        for (int kk = 0; kk < KC; kk++) {
            ulonglong2 a = *reinterpret_cast<const ulonglong2*>(&As2[p][kk][ty * 2]);
            ulonglong2 b = *reinterpret_cast<const ulonglong2*>(&Bs[p][kk][tx * 4]);
            ffma2(acc[0][0], a.x, b.x); ffma2(acc[0][1], a.x, b.y);
            ffma2(acc[1][0], a.y, b.x); ffma2(acc[1][1], a.y, b.y);
        }
        if (c + 1 < NCH) {
            int q = p ^ 1;
            As2[q][akq + 0][anode] = dup2(aReg.x); As2[q][akq + 1][anode] = dup2(aReg.y);
            As2[q][akq + 2][anode] = dup2(aReg.z); As2[q][akq + 3][anode] = dup2(aReg.w);
            *reinterpret_cast<float4*>(&Bs[q][bk][bo])     = bR0;
            *reinterpret_cast<float4*>(&Bs[q][bk][bo + 4]) = bR1;
        }
        p ^= 1;
    }

    float* P = g_part + (((size_t)br * KSPL + kz) * NND + n0) * OUTC;
#pragma unroll
    for (int r = 0; r < 2; r++) {
        float2 v0, v1;
        memcpy(&v0, &acc[r][0], 8);
        memcpy(&v1, &acc[r][1], 8);
        float4 o = make_float4(v0.x, v0.y, v1.x, v1.y);
        *reinterpret_cast<float4*>(&P[(ty * 2 + r) * OUTC + tx * 4]) = o;
    }
}

// ---------------- 6) combine: out = 0.5*((sum parts)/9 + xmg@b2g + xmf@b2f) ----
__global__ __launch_bounds__(256) void combine_kernel(
    const float* __restrict__ b2g, const float* __restrict__ b2f,
    float* __restrict__ out) {
    __shared__ float s_b2[2][INC * OUTC];   // 16 KB
    __shared__ float s_xm[2][4][INC];

    int tid = threadIdx.x;
    int nl = tid >> 6, o = tid & 63;
    int n = blockIdx.x * 4 + nl;

    for (int v = tid; v < INC * OUTC; v += 256) {
        s_b2[0][v] = b2g[v];
        s_b2[1][v] = b2f[v];
    }
    {
        int br = tid >> 7, nn = (tid >> 5) & 3, i = tid & 31;
        s_xm[br][nn][i] = g_xjm[br][(size_t)(blockIdx.x * 4 + nn) * INC + i];
    }
    __syncthreads();

    float val = ((g_part[((size_t)0 * NND + n) * OUTC + o]  +
                  g_part[((size_t)1 * NND + n) * OUTC + o]) +
                 (g_part[((size_t)2 * NND + n) * OUTC + o]  +
                  g_part[((size_t)3 * NND + n) * OUTC + o])) * (1.0f / 9.0f);
#pragma unroll
    for (int br = 0; br < 2; br++)
#pragma unroll
        for (int i = 0; i < INC; i++)
            val = fmaf(s_xm[br][nl][i], s_b2[br][i * OUTC + o], val);
    out[(size_t)n * OUTC + o] = 0.5f * val;
}

// ---------------- launch -------------------------------------------------------
extern "C" void kernel_launch(void* const* d_in, const int* in_sizes, int n_in,
                              void* d_out, int out_size) {
    const float* x   = (const float*)d_in[0];
    const float* pos = (const float*)d_in[1];
    const float* w1g = (const float*)d_in[2];
    const float* b1g = (const float*)d_in[3];
    const float* w2g = (const float*)d_in[4];
    const float* b2g = (const float*)d_in[5];
    const float* w1f = (const float*)d_in[6];
    const float* b1f = (const float*)d_in[7];
    const float* w2f = (const float*)d_in[8];
    const float* b2f = (const float*)d_in[9];
    float* out = (float*)d_out;

    knn_pos_kernel<<<dim3(NND / 8, 2), 256>>>(pos);
    knn_feat_kernel<<<dim3(NND / 16, 4), 256>>>(x);
    knn_mergeP_kernel<<<2 * NND / 256, 256>>>();
    buildS_kernel<<<dim3(NND, 2), 128>>>(x, pos, w1g, b1g, w1f, b1f);
    gemm_kernel<<<dim3(NND / 32, 2, KSPL), 256>>>(w2g, w2f);
    combine_kernel<<<NND / 4, 256>>>(b2g, b2f, out);
}

// round 6
// speedup vs baseline: 1.3463x; 1.3463x over previous
#include <cuda_runtime.h>
#include <cuda_bf16.h>
#include <math.h>
#include <string.h>
#include <stdint.h>

#define NND   4096
#define KNBR  9
#define INC   32
#define OUTC  64
#define HID   128
#define SDIM  4096
#define KSPL  4
#define KLEN  (SDIM / KSPL)   // 1024
#define KC    64
#define AST   72              // smem row stride (bf16) -> conflict-free frags

// ---------------- scratch (static device globals; no allocation) ----------------
__device__ int   g_idx[2][NND * KNBR];
__device__ float g_pd[2][4][NND][KNBR];
__device__ int   g_pi[2][4][NND][KNBR];
__device__ __nv_bfloat16 g_Sh[2][(size_t)NND * SDIM];   // 32 MB
__device__ __nv_bfloat16 g_Sl[2][(size_t)NND * SDIM];   // 32 MB
__device__ __nv_bfloat16 g_Wth[2][OUTC * SDIM];         // W^T hi [o][k]
__device__ __nv_bfloat16 g_Wtl[2][OUTC * SDIM];         // W^T lo [o][k]
__device__ float g_xjm[2][NND * INC];
__device__ float g_part[2][KSPL][NND][OUTC];

// ======================= KNN (known-good from R4) ==============================
__device__ __forceinline__ bool knn_less(float d, int i, float d2, int i2) {
    return (d < d2) || (d == d2 && i < i2);
}
__device__ __forceinline__ void knn_insert(float dist, int j, float bd[KNBR], int bi[KNBR]) {
    if (knn_less(dist, j, bd[KNBR - 1], bi[KNBR - 1])) {
        float cd = dist; int ci = j;
#pragma unroll
        for (int r = 0; r < KNBR; r++) {
            bool sw = knn_less(cd, ci, bd[r], bi[r]);
            float td = bd[r]; int ti = bi[r];
            if (sw) { bd[r] = cd; bi[r] = ci; cd = td; ci = ti; }
        }
    }
}
__device__ __forceinline__ void knn_merge_warp(float* md, int* mi, const float bd[KNBR],
                                               const int bi[KNBR], int lane,
                                               float* opd, int* opi, int q) {
#pragma unroll
    for (int r = 0; r < KNBR; r++) { md[lane * KNBR + r] = bd[r]; mi[lane * KNBR + r] = bi[r]; }
    __syncwarp();
    int p = 0;
    for (int r = 0; r < KNBR; r++) {
        float cd = (p < KNBR) ? md[lane * KNBR + p] : 3.4e38f;
        int   ci = (p < KNBR) ? mi[lane * KNBR + p] : 0x7FFFFFFF;
        float rd = cd; int ri = ci;
#pragma unroll
        for (int off = 16; off; off >>= 1) {
            float od = __shfl_xor_sync(0xFFFFFFFFu, rd, off);
            int   oi = __shfl_xor_sync(0xFFFFFFFFu, ri, off);
            if (knn_less(od, oi, rd, ri)) { rd = od; ri = oi; }
        }
        if (ci == ri && p < KNBR) p++;
        if (lane == 0) { opd[q * KNBR + r] = rd; opi[q * KNBR + r] = ri; }
    }
    __syncwarp();
}

#define PPART (NND / 2)
__global__ __launch_bounds__(256) void knn_pos_kernel(const float* __restrict__ pos) {
    __shared__ float smem[PPART * 3];
    int t = threadIdx.x, w = t >> 5, lane = t & 31;
    int q = blockIdx.x * 8 + w;
    int part = blockIdx.y;
    int base = part * PPART;

    for (int v = t; v < PPART * 3; v += 256) smem[v] = pos[base * 3 + v];
    __syncthreads();

    float q0 = pos[q * 3 + 0], q1 = pos[q * 3 + 1], q2 = pos[q * 3 + 2];
    float sqq = 0.f;
    sqq = fmaf(q0, q0, sqq); sqq = fmaf(q1, q1, sqq); sqq = fmaf(q2, q2, sqq);

    float bd[KNBR]; int bi[KNBR];
#pragma unroll
    for (int r = 0; r < KNBR; r++) { bd[r] = 3.4e38f; bi[r] = 0x7FFFFFFF; }

    for (int jl = lane; jl < PPART; jl += 32) {
        float c0 = smem[jl * 3 + 0], c1 = smem[jl * 3 + 1], c2 = smem[jl * 3 + 2];
        float acc = 0.f;
        acc = fmaf(q0, c0, acc); acc = fmaf(q1, c1, acc); acc = fmaf(q2, c2, acc);
        float sqj = 0.f;
        sqj = fmaf(c0, c0, sqj); sqj = fmaf(c1, c1, sqj); sqj = fmaf(c2, c2, sqj);
        knn_insert((sqq + sqj) - 2.0f * acc, base + jl, bd, bi);
    }
    __syncthreads();

    float* md = smem + (size_t)w * 288;
    int*   mi = (int*)(smem + 8 * 288) + (size_t)w * 288;
    knn_merge_warp(md, mi, bd, bi, lane, &g_pd[0][part][0][0], &g_pi[0][part][0][0], q);
}

#define TS 256
#define FPART (NND / 4)
__global__ __launch_bounds__(256) void knn_feat_kernel(const float* __restrict__ x) {
    __shared__ float s_tile[TS * 33];
    __shared__ float s_sq[TS];
    int t = threadIdx.x, w = t >> 5, lane = t & 31;
    int qa_i = blockIdx.x * 16 + w * 2;
    int qb_i = qa_i + 1;
    int part = blockIdx.y;
    int base0 = part * FPART;

    float qa[INC], qb[INC];
#pragma unroll
    for (int d = 0; d < INC; d++) qa[d] = x[qa_i * INC + d];
#pragma unroll
    for (int d = 0; d < INC; d++) qb[d] = x[qb_i * INC + d];
    float sqa = 0.f, sqb = 0.f;
#pragma unroll
    for (int d = 0; d < INC; d++) sqa = fmaf(qa[d], qa[d], sqa);
#pragma unroll
    for (int d = 0; d < INC; d++) sqb = fmaf(qb[d], qb[d], sqb);

    float bda[KNBR], bdb[KNBR]; int bia[KNBR], bib[KNBR];
#pragma unroll
    for (int r = 0; r < KNBR; r++) {
        bda[r] = 3.4e38f; bia[r] = 0x7FFFFFFF;
        bdb[r] = 3.4e38f; bib[r] = 0x7FFFFFFF;
    }

    for (int base = base0; base < base0 + FPART; base += TS) {
        __syncthreads();
#pragma unroll
        for (int v = t; v < TS * INC; v += 256) {
            int r = v >> 5, d = v & 31;
            s_tile[r * 33 + d] = x[(size_t)(base + r) * INC + d];
        }
        __syncthreads();
        {
            float s = 0.f;
#pragma unroll
            for (int d = 0; d < INC; d++) { float v = s_tile[t * 33 + d]; s = fmaf(v, v, s); }
            s_sq[t] = s;
        }
        __syncthreads();

        for (int s = 0; s < TS; s += 32) {
            int r = s + lane;
            int j = base + r;
            const float* c = &s_tile[r * 33];
            float acc0 = 0.f, acc1 = 0.f;
#pragma unroll
            for (int d = 0; d < INC; d++) {
                float cv = c[d];
                acc0 = fmaf(qa[d], cv, acc0);
                acc1 = fmaf(qb[d], cv, acc1);
            }
            float sqj = s_sq[r];
            knn_insert((sqa + sqj) - 2.0f * acc0, j, bda, bia);
            knn_insert((sqb + sqj) - 2.0f * acc1, j, bdb, bib);
        }
    }
    __syncthreads();

    float* md = s_tile + (size_t)w * 288;
    int*   mi = (int*)(s_tile + 8 * 288) + (size_t)w * 288;
    knn_merge_warp(md, mi, bda, bia, lane, &g_pd[1][part][0][0], &g_pi[1][part][0][0], qa_i);
    knn_merge_warp(md, mi, bdb, bib, lane, &g_pd[1][part][0][0], &g_pi[1][part][0][0], qb_i);
}

template <int BR, int P>
__global__ __launch_bounds__(256) void knn_mergeP_kernel() {
    int q = blockIdx.x * 256 + threadIdx.x;
    int p[4] = {0, 0, 0, 0};
    for (int r = 0; r < KNBR; r++) {
        float bd = 3.4e38f; int bi = 0x7FFFFFFF, bt = 0;
#pragma unroll
        for (int t = 0; t < P; t++) {
            float d = g_pd[BR][t][q][p[t]];
            int   i = g_pi[BR][t][q][p[t]];
            if (knn_less(d, i, bd, bi)) { bd = d; bi = i; bt = t; }
        }
        p[bt]++;
        g_idx[BR][q * KNBR + r] = bi;
    }
}

// ================= buildS: attrs -> h -> S (bf16 hi/lo), xjmean =================
__global__ __launch_bounds__(128) void buildS_kernel(
    const float* __restrict__ x, const float* __restrict__ pos,
    const float* __restrict__ w1, const float* __restrict__ b1, int br) {
    int n = blockIdx.x;
    int t = threadIdx.x;

    __shared__ int   s_idx[KNBR];
    __shared__ float s_xj[KNBR][INC];
    __shared__ float s_attr[KNBR][3];
    __shared__ float s_h[KNBR][HID];
    __shared__ float s_pn[3];

    const int* idx = g_idx[br];

    if (t < KNBR) s_idx[t] = idx[n * KNBR + t];
    if (t < 3)    s_pn[t] = pos[n * 3 + t];
    __syncthreads();

    for (int v = t; v < KNBR * INC; v += 128)
        s_xj[v / INC][v % INC] = x[(size_t)s_idx[v / INC] * INC + (v % INC)];

    if (t < KNBR) {
        int sj = s_idx[t];
        float cx = pos[sj * 3 + 0] - s_pn[0];
        float cy = pos[sj * 3 + 1] - s_pn[1];
        float cz = pos[sj * 3 + 2] - s_pn[2];
        float rho = sqrtf((cx * cx + cy * cy) + cz * cz);
        float th  = atan2f(cy, cx);
        float ratio = cz / fmaxf(rho, 1e-12f);
        ratio = fminf(1.0f, fmaxf(-1.0f, ratio));
        float ph = acosf(ratio);
        s_attr[t][0] = rho; s_attr[t][1] = th; s_attr[t][2] = ph;
    }
    __syncthreads();

    {
        int c = t;
        float wa = w1[c], wb = w1[HID + c], wc = w1[2 * HID + c], bb = b1[c];
        float hk[KNBR];
#pragma unroll
        for (int k = 0; k < KNBR; k++)
            hk[k] = tanhf(bb + s_attr[k][0] * wa + s_attr[k][1] * wb + s_attr[k][2] * wc);
#pragma unroll
        for (int k = 0; k < KNBR; k++) s_h[k][c] = hk[k];
    }
    __syncthreads();

    int w = t >> 5, lane = t & 31;
    __nv_bfloat16* Sh = g_Sh[br] + (size_t)n * SDIM;
    __nv_bfloat16* Sl = g_Sl[br] + (size_t)n * SDIM;
    for (int j = 0; j < 32; j++) {
        int c = w * 32 + j;
        float s = 0.f;
#pragma unroll
        for (int k = 0; k < KNBR; k++) s = fmaf(s_h[k][c], s_xj[k][lane], s);
        __nv_bfloat16 h = __float2bfloat16(s);
        __nv_bfloat16 l = __float2bfloat16(s - __bfloat162float(h));
        Sh[c * INC + lane] = h;
        Sl[c * INC + lane] = l;
    }
    if (t < INC) {
        float m = 0.f;
#pragma unroll
        for (int k = 0; k < KNBR; k++) m += s_xj[k][t];
        g_xjm[br][n * INC + t] = m * (1.0f / 9.0f);
    }
}

// ================= transpose + split W2 -> Wt hi/lo [o][k] =====================
__global__ __launch_bounds__(256) void transposeW_kernel(
    const float* __restrict__ w2g, const float* __restrict__ w2f) {
    int kt = blockIdx.x, br = blockIdx.y;
    const float* W = br ? w2f : w2g;
    __shared__ float tile[64][65];
    int t = threadIdx.x;
    for (int v = t; v < 64 * 64; v += 256) {
        int kk = v >> 6, o = v & 63;
        tile[kk][o] = W[(size_t)(kt * 64 + kk) * 64 + o];
    }
    __syncthreads();
    for (int v = t; v < 64 * 64; v += 256) {
        int o = v >> 6, kk = v & 63;
        float f = tile[kk][o];
        __nv_bfloat16 h = __float2bfloat16(f);
        __nv_bfloat16 l = __float2bfloat16(f - __bfloat162float(h));
        g_Wth[br][(size_t)o * SDIM + kt * 64 + kk] = h;
        g_Wtl[br][(size_t)o * SDIM + kt * 64 + kk] = l;
    }
}

// ================= GEMM via mma.sync bf16 (hi/lo 3-term) =======================
__device__ __forceinline__ void mma_bf16(float* c, const uint32_t* a, const uint32_t* b) {
    asm volatile(
        "mma.sync.aligned.m16n8k16.row.col.f32.bf16.bf16.f32 "
        "{%0,%1,%2,%3}, {%4,%5,%6,%7}, {%8,%9}, {%0,%1,%2,%3};"
        : "+f"(c[0]), "+f"(c[1]), "+f"(c[2]), "+f"(c[3])
        : "r"(a[0]), "r"(a[1]), "r"(a[2]), "r"(a[3]), "r"(b[0]), "r"(b[1]));
}

#define GSMEM_BYTES ((128 * AST * 2 + 64 * AST * 2) * 2)   // 55296 B

__global__ __launch_bounds__(256) void gemm_kernel() {
    extern __shared__ __align__(16) __nv_bfloat16 sm[];
    __nv_bfloat16* Ah = sm;                  // 128 x AST
    __nv_bfloat16* Al = Ah + 128 * AST;
    __nv_bfloat16* Bh = Al + 128 * AST;      // 64 x AST
    __nv_bfloat16* Bl = Bh + 64 * AST;

    int tid = threadIdx.x, warp = tid >> 5, lane = tid & 31;
    int br = blockIdx.y, kz = blockIdx.z;
    int n0 = blockIdx.x * 128;
    int kbase = kz * KLEN;
    int mw = warp >> 1, nw = warp & 1;       // warp tile: m32 x n32
    int g = lane >> 2, t = lane & 3;

    const __nv_bfloat16* ShG = g_Sh[br];
    const __nv_bfloat16* SlG = g_Sl[br];
    const __nv_bfloat16* WhG = g_Wth[br];
    const __nv_bfloat16* WlG = g_Wtl[br];

    float acc[2][4][4];
#pragma unroll
    for (int mi = 0; mi < 2; mi++)
#pragma unroll
        for (int ni = 0; ni < 4; ni++)
#pragma unroll
            for (int e = 0; e < 4; e++) acc[mi][ni][e] = 0.f;

    for (int c = 0; c < KLEN / KC; c++) {
        int koff = kbase + c * KC;
        __syncthreads();
        // stage A hi/lo: 128 rows x 8 16B-units
#pragma unroll
        for (int u = tid; u < 1024; u += 256) {
            int m = u >> 3, j = u & 7;
            size_t s = (size_t)(n0 + m) * SDIM + koff + j * 8;
            *reinterpret_cast<uint4*>(&Ah[m * AST + j * 8]) =
                *reinterpret_cast<const uint4*>(&ShG[s]);
            *reinterpret_cast<uint4*>(&Al[m * AST + j * 8]) =
                *reinterpret_cast<const uint4*>(&SlG[s]);
        }
        // stage B hi/lo: 64 rows x 8 16B-units
#pragma unroll
        for (int u = tid; u < 512; u += 256) {
            int o = u >> 3, j = u & 7;
            size_t s = (size_t)o * SDIM + koff + j * 8;
            *reinterpret_cast<uint4*>(&Bh[o * AST + j * 8]) =
                *reinterpret_cast<const uint4*>(&WhG[s]);
            *reinterpret_cast<uint4*>(&Bl[o * AST + j * 8]) =
                *reinterpret_cast<const uint4*>(&WlG[s]);
        }
        __syncthreads();

#pragma unroll
        for (int ks = 0; ks < KC / 16; ks++) {
            int k0 = ks * 16;
            uint32_t ah[2][4], al[2][4], bh[4][2], bl[4][2];
#pragma unroll
            for (int mi = 0; mi < 2; mi++) {
                int r0 = mw * 32 + mi * 16;
                ah[mi][0] = *reinterpret_cast<const uint32_t*>(&Ah[(r0 + g) * AST + k0 + 2 * t]);
                ah[mi][1] = *reinterpret_cast<const uint32_t*>(&Ah[(r0 + g + 8) * AST + k0 + 2 * t]);
                ah[mi][2] = *reinterpret_cast<const uint32_t*>(&Ah[(r0 + g) * AST + k0 + 2 * t + 8]);
                ah[mi][3] = *reinterpret_cast<const uint32_t*>(&Ah[(r0 + g + 8) * AST + k0 + 2 * t + 8]);
                al[mi][0] = *reinterpret_cast<const uint32_t*>(&Al[(r0 + g) * AST + k0 + 2 * t]);
                al[mi][1] = *reinterpret_cast<const uint32_t*>(&Al[(r0 + g + 8) * AST + k0 + 2 * t]);
                al[mi][2] = *reinterpret_cast<const uint32_t*>(&Al[(r0 + g) * AST + k0 + 2 * t + 8]);
                al[mi][3] = *reinterpret_cast<const uint32_t*>(&Al[(r0 + g + 8) * AST + k0 + 2 * t + 8]);
            }
#pragma unroll
            for (int ni = 0; ni < 4; ni++) {
                int o0 = nw * 32 + ni * 8;
                bh[ni][0] = *reinterpret_cast<const uint32_t*>(&Bh[(o0 + g) * AST + k0 + 2 * t]);
                bh[ni][1] = *reinterpret_cast<const uint32_t*>(&Bh[(o0 + g) * AST + k0 + 2 * t + 8]);
                bl[ni][0] = *reinterpret_cast<const uint32_t*>(&Bl[(o0 + g) * AST + k0 + 2 * t]);
                bl[ni][1] = *reinterpret_cast<const uint32_t*>(&Bl[(o0 + g) * AST + k0 + 2 * t + 8]);
            }
#pragma unroll
            for (int mi = 0; mi < 2; mi++)
#pragma unroll
                for (int ni = 0; ni < 4; ni++) {
                    mma_bf16(acc[mi][ni], ah[mi], bh[ni]);
                    mma_bf16(acc[mi][ni], ah[mi], bl[ni]);
                    mma_bf16(acc[mi][ni], al[mi], bh[ni]);
                }
        }
    }

    float* P = &g_part[br][kz][0][0];
#pragma unroll
    for (int mi = 0; mi < 2; mi++) {
        int r0 = mw * 32 + mi * 16;
#pragma unroll
        for (int ni = 0; ni < 4; ni++) {
            int col = nw * 32 + ni * 8 + 2 * t;
            float2 v01 = make_float2(acc[mi][ni][0], acc[mi][ni][1]);
            float2 v23 = make_float2(acc[mi][ni][2], acc[mi][ni][3]);
            *reinterpret_cast<float2*>(&P[(size_t)(n0 + r0 + g) * OUTC + col]) = v01;
            *reinterpret_cast<float2*>(&P[(size_t)(n0 + r0 + g + 8) * OUTC + col]) = v23;
        }
    }
}

// ================= combine: out = 0.5*((sum parts)/9 + xm@b2 both) =============
__global__ __launch_bounds__(256) void combine_kernel(
    const float* __restrict__ b2g, const float* __restrict__ b2f,
    float* __restrict__ out) {
    __shared__ float s_b2[2][INC * OUTC];
    __shared__ float s_xm[2][4][INC];

    int tid = threadIdx.x;
    int nl = tid >> 6, o = tid & 63;
    int n = blockIdx.x * 4 + nl;

    for (int v = tid; v < INC * OUTC; v += 256) {
        s_b2[0][v] = b2g[v];
        s_b2[1][v] = b2f[v];
    }
    {
        int br = tid >> 7, nn = (tid >> 5) & 3, i = tid & 31;
        s_xm[br][nn][i] = g_xjm[br][(size_t)(blockIdx.x * 4 + nn) * INC + i];
    }
    __syncthreads();

    float val = 0.f;
#pragma unroll
    for (int br = 0; br < 2; br++)
#pragma unroll
        for (int kzi = 0; kzi < KSPL; kzi++)
            val += g_part[br][kzi][n][o];
    val *= (1.0f / 9.0f);
#pragma unroll
    for (int br = 0; br < 2; br++)
#pragma unroll
        for (int i = 0; i < INC; i++)
            val = fmaf(s_xm[br][nl][i], s_b2[br][i * OUTC + o], val);
    out[(size_t)n * OUTC + o] = 0.5f * val;
}

// ---------------- launch -------------------------------------------------------
extern "C" void kernel_launch(void* const* d_in, const int* in_sizes, int n_in,
                              void* d_out, int out_size) {
    const float* x   = (const float*)d_in[0];
    const float* pos = (const float*)d_in[1];
    const float* w1g = (const float*)d_in[2];
    const float* b1g = (const float*)d_in[3];
    const float* w2g = (const float*)d_in[4];
    const float* b2g = (const float*)d_in[5];
    const float* w1f = (const float*)d_in[6];
    const float* b1f = (const float*)d_in[7];
    const float* w2f = (const float*)d_in[8];
    const float* b2f = (const float*)d_in[9];
    float* out = (float*)d_out;

    cudaFuncSetAttribute(gemm_kernel, cudaFuncAttributeMaxDynamicSharedMemorySize,
                         GSMEM_BYTES);

    knn_pos_kernel<<<dim3(NND / 8, 2), 256>>>(pos);                   // 0
    knn_mergeP_kernel<0, 2><<<NND / 256, 256>>>();                    // 1
    buildS_kernel<<<NND, 128>>>(x, pos, w1g, b1g, 0);                 // 2
    knn_feat_kernel<<<dim3(NND / 16, 4), 256>>>(x);                   // 3  <- profiled
    knn_mergeP_kernel<1, 4><<<NND / 256, 256>>>();                    // 4
    buildS_kernel<<<NND, 128>>>(x, pos, w1f, b1f, 1);                 // 5
    transposeW_kernel<<<dim3(SDIM / 64, 2), 256>>>(w2g, w2f);         // 6
    gemm_kernel<<<dim3(NND / 128, 2, KSPL), 256, GSMEM_BYTES>>>();    // 7
    combine_kernel<<<NND / 4, 256>>>(b2g, b2f, out);                  // 8
}

// round 7
// speedup vs baseline: 1.3568x; 1.0078x over previous
#include <cuda_runtime.h>
#include <cuda_bf16.h>
#include <math.h>
#include <string.h>
#include <stdint.h>

#define NND   4096
#define KNBR  9
#define INC   32
#define OUTC  64
#define HID   128
#define SDIM  4096
#define KSPL  4
#define KLEN  (SDIM / KSPL)   // 1024
#define KC    64
#define AST   72              // smem row stride (bf16) -> conflict-free frags

// ---------------- scratch (static device globals; no allocation) ----------------
__device__ int   g_idx[2][NND * KNBR];
__device__ float g_pd[2][4][NND][KNBR];
__device__ int   g_pi[2][4][NND][KNBR];
__device__ __nv_bfloat16 g_Sh[2][(size_t)NND * SDIM];   // 32 MB
__device__ __nv_bfloat16 g_Sl[2][(size_t)NND * SDIM];   // 32 MB
__device__ __nv_bfloat16 g_Wth[2][OUTC * SDIM];         // W^T hi [o][k]
__device__ __nv_bfloat16 g_Wtl[2][OUTC * SDIM];         // W^T lo [o][k]
__device__ float g_xjm[2][NND * INC];
__device__ float g_part[2][KSPL][NND][OUTC];

// ======================= KNN helpers ===========================================
__device__ __forceinline__ bool knn_less(float d, int i, float d2, int i2) {
    return (d < d2) || (d == d2 && i < i2);
}
__device__ __forceinline__ void knn_insert(float dist, int j, float bd[KNBR], int bi[KNBR]) {
    if (knn_less(dist, j, bd[KNBR - 1], bi[KNBR - 1])) {
        float cd = dist; int ci = j;
#pragma unroll
        for (int r = 0; r < KNBR; r++) {
            bool sw = knn_less(cd, ci, bd[r], bi[r]);
            float td = bd[r]; int ti = bi[r];
            if (sw) { bd[r] = cd; bi[r] = ci; cd = td; ci = ti; }
        }
    }
}
__device__ __forceinline__ void knn_merge_warp(float* md, int* mi, const float bd[KNBR],
                                               const int bi[KNBR], int lane,
                                               float* opd, int* opi, int q) {
#pragma unroll
    for (int r = 0; r < KNBR; r++) { md[lane * KNBR + r] = bd[r]; mi[lane * KNBR + r] = bi[r]; }
    __syncwarp();
    int p = 0;
    for (int r = 0; r < KNBR; r++) {
        float cd = (p < KNBR) ? md[lane * KNBR + p] : 3.4e38f;
        int   ci = (p < KNBR) ? mi[lane * KNBR + p] : 0x7FFFFFFF;
        float rd = cd; int ri = ci;
#pragma unroll
        for (int off = 16; off; off >>= 1) {
            float od = __shfl_xor_sync(0xFFFFFFFFu, rd, off);
            int   oi = __shfl_xor_sync(0xFFFFFFFFu, ri, off);
            if (knn_less(od, oi, rd, ri)) { rd = od; ri = oi; }
        }
        if (ci == ri && p < KNBR) p++;
        if (lane == 0) { opd[q * KNBR + r] = rd; opi[q * KNBR + r] = ri; }
    }
    __syncwarp();
}

// ---------------- KNN on pos: part-split, 4 candidates in flight per lane -------
#define PPART (NND / 2)
__global__ __launch_bounds__(256) void knn_pos_kernel(const float* __restrict__ pos) {
    __shared__ float smem[PPART * 3];
    int t = threadIdx.x, w = t >> 5, lane = t & 31;
    int q = blockIdx.x * 8 + w;
    int part = blockIdx.y;
    int base = part * PPART;

    for (int v = t; v < PPART * 3; v += 256) smem[v] = pos[base * 3 + v];
    __syncthreads();

    float q0 = pos[q * 3 + 0], q1 = pos[q * 3 + 1], q2 = pos[q * 3 + 2];
    float sqq = 0.f;
    sqq = fmaf(q0, q0, sqq); sqq = fmaf(q1, q1, sqq); sqq = fmaf(q2, q2, sqq);

    float bd[KNBR]; int bi[KNBR];
#pragma unroll
    for (int r = 0; r < KNBR; r++) { bd[r] = 3.4e38f; bi[r] = 0x7FFFFFFF; }

    // 4 candidates per lane-iteration: independent chains hide FMA latency
    for (int jl = lane; jl < PPART; jl += 128) {
        float dist[4];
#pragma unroll
        for (int u = 0; u < 4; u++) {
            int jj = jl + u * 32;
            float c0 = smem[jj * 3 + 0], c1 = smem[jj * 3 + 1], c2 = smem[jj * 3 + 2];
            float acc = 0.f;
            acc = fmaf(q0, c0, acc); acc = fmaf(q1, c1, acc); acc = fmaf(q2, c2, acc);
            float sqj = 0.f;
            sqj = fmaf(c0, c0, sqj); sqj = fmaf(c1, c1, sqj); sqj = fmaf(c2, c2, sqj);
            dist[u] = (sqq + sqj) - 2.0f * acc;
        }
#pragma unroll
        for (int u = 0; u < 4; u++) knn_insert(dist[u], base + jl + u * 32, bd, bi);
    }
    __syncthreads();

    float* md = smem + (size_t)w * 288;
    int*   mi = (int*)(smem + 8 * 288) + (size_t)w * 288;
    knn_merge_warp(md, mi, bd, bi, lane, &g_pd[0][part][0][0], &g_pi[0][part][0][0], q);
}

// ---------------- KNN on x: 4-partial accumulator chains per query --------------
#define TS 256
#define FPART (NND / 4)
// identical 4-partial reduction everywhere -> self-distance bitwise 0
__device__ __forceinline__ float dot4split(const float* __restrict__ qv,
                                           const float* __restrict__ c) {
    float a0 = 0.f, a1 = 0.f, a2 = 0.f, a3 = 0.f;
#pragma unroll
    for (int dd = 0; dd < 8; dd++) {
        a0 = fmaf(qv[dd],      c[dd],      a0);
        a1 = fmaf(qv[8 + dd],  c[8 + dd],  a1);
        a2 = fmaf(qv[16 + dd], c[16 + dd], a2);
        a3 = fmaf(qv[24 + dd], c[24 + dd], a3);
    }
    return (a0 + a1) + (a2 + a3);
}

__global__ __launch_bounds__(256) void knn_feat_kernel(const float* __restrict__ x) {
    __shared__ float s_tile[TS * 33];
    __shared__ float s_sq[TS];
    int t = threadIdx.x, w = t >> 5, lane = t & 31;
    int qa_i = blockIdx.x * 16 + w * 2;
    int qb_i = qa_i + 1;
    int part = blockIdx.y;
    int base0 = part * FPART;

    float qa[INC], qb[INC];
#pragma unroll
    for (int d = 0; d < INC; d++) qa[d] = x[qa_i * INC + d];
#pragma unroll
    for (int d = 0; d < INC; d++) qb[d] = x[qb_i * INC + d];
    float sqa = dot4split(qa, qa);
    float sqb = dot4split(qb, qb);

    float bda[KNBR], bdb[KNBR]; int bia[KNBR], bib[KNBR];
#pragma unroll
    for (int r = 0; r < KNBR; r++) {
        bda[r] = 3.4e38f; bia[r] = 0x7FFFFFFF;
        bdb[r] = 3.4e38f; bib[r] = 0x7FFFFFFF;
    }

    for (int base = base0; base < base0 + FPART; base += TS) {
        __syncthreads();
#pragma unroll
        for (int v = t; v < TS * INC; v += 256) {
            int r = v >> 5, d = v & 31;
            s_tile[r * 33 + d] = x[(size_t)(base + r) * INC + d];
        }
        __syncthreads();
        s_sq[t] = dot4split(&s_tile[t * 33], &s_tile[t * 33]);
        __syncthreads();

        for (int s = 0; s < TS; s += 32) {
            int r = s + lane;
            int j = base + r;
            const float* c = &s_tile[r * 33];
            // 8 independent FMA chains (4 per query)
            float a0 = 0.f, a1 = 0.f, a2 = 0.f, a3 = 0.f;
            float b0 = 0.f, b1 = 0.f, b2 = 0.f, b3 = 0.f;
#pragma unroll
            for (int dd = 0; dd < 8; dd++) {
                float c0 = c[dd], c1 = c[8 + dd], c2 = c[16 + dd], c3 = c[24 + dd];
                a0 = fmaf(qa[dd],      c0, a0);
                a1 = fmaf(qa[8 + dd],  c1, a1);
                a2 = fmaf(qa[16 + dd], c2, a2);
                a3 = fmaf(qa[24 + dd], c3, a3);
                b0 = fmaf(qb[dd],      c0, b0);
                b1 = fmaf(qb[8 + dd],  c1, b1);
                b2 = fmaf(qb[16 + dd], c2, b2);
                b3 = fmaf(qb[24 + dd], c3, b3);
            }
            float acc0 = (a0 + a1) + (a2 + a3);
            float acc1 = (b0 + b1) + (b2 + b3);
            float sqj = s_sq[r];
            knn_insert((sqa + sqj) - 2.0f * acc0, j, bda, bia);
            knn_insert((sqb + sqj) - 2.0f * acc1, j, bdb, bib);
        }
    }
    __syncthreads();

    float* md = s_tile + (size_t)w * 288;
    int*   mi = (int*)(s_tile + 8 * 288) + (size_t)w * 288;
    knn_merge_warp(md, mi, bda, bia, lane, &g_pd[1][part][0][0], &g_pi[1][part][0][0], qa_i);
    knn_merge_warp(md, mi, bdb, bib, lane, &g_pd[1][part][0][0], &g_pi[1][part][0][0], qb_i);
}

template <int BR, int P>
__global__ __launch_bounds__(256) void knn_mergeP_kernel() {
    int q = blockIdx.x * 256 + threadIdx.x;
    int p[4] = {0, 0, 0, 0};
    for (int r = 0; r < KNBR; r++) {
        float bd = 3.4e38f; int bi = 0x7FFFFFFF, bt = 0;
#pragma unroll
        for (int t = 0; t < P; t++) {
            float d = g_pd[BR][t][q][p[t]];
            int   i = g_pi[BR][t][q][p[t]];
            if (knn_less(d, i, bd, bi)) { bd = d; bi = i; bt = t; }
        }
        p[bt]++;
        g_idx[BR][q * KNBR + r] = bi;
    }
}

// ================= buildS: attrs -> h -> S (bf16 hi/lo), xjmean =================
__global__ __launch_bounds__(128) void buildS_kernel(
    const float* __restrict__ x, const float* __restrict__ pos,
    const float* __restrict__ w1, const float* __restrict__ b1, int br) {
    int n = blockIdx.x;
    int t = threadIdx.x;

    __shared__ int   s_idx[KNBR];
    __shared__ float s_xj[KNBR][INC];
    __shared__ float s_attr[KNBR][3];
    __shared__ float s_h[KNBR][HID];
    __shared__ float s_pn[3];

    const int* idx = g_idx[br];

    if (t < KNBR) s_idx[t] = idx[n * KNBR + t];
    if (t < 3)    s_pn[t] = pos[n * 3 + t];
    __syncthreads();

    for (int v = t; v < KNBR * INC; v += 128)
        s_xj[v / INC][v % INC] = x[(size_t)s_idx[v / INC] * INC + (v % INC)];

    if (t < KNBR) {
        int sj = s_idx[t];
        float cx = pos[sj * 3 + 0] - s_pn[0];
        float cy = pos[sj * 3 + 1] - s_pn[1];
        float cz = pos[sj * 3 + 2] - s_pn[2];
        float rho = sqrtf((cx * cx + cy * cy) + cz * cz);
        float th  = atan2f(cy, cx);
        float ratio = cz / fmaxf(rho, 1e-12f);
        ratio = fminf(1.0f, fmaxf(-1.0f, ratio));
        float ph = acosf(ratio);
        s_attr[t][0] = rho; s_attr[t][1] = th; s_attr[t][2] = ph;
    }
    __syncthreads();

    {
        int c = t;
        float wa = w1[c], wb = w1[HID + c], wc = w1[2 * HID + c], bb = b1[c];
        float hk[KNBR];
#pragma unroll
        for (int k = 0; k < KNBR; k++)
            hk[k] = tanhf(bb + s_attr[k][0] * wa + s_attr[k][1] * wb + s_attr[k][2] * wc);
#pragma unroll
        for (int k = 0; k < KNBR; k++) s_h[k][c] = hk[k];
    }
    __syncthreads();

    int w = t >> 5, lane = t & 31;
    __nv_bfloat16* Sh = g_Sh[br] + (size_t)n * SDIM;
    __nv_bfloat16* Sl = g_Sl[br] + (size_t)n * SDIM;
    for (int j = 0; j < 32; j++) {
        int c = w * 32 + j;
        float s = 0.f;
#pragma unroll
        for (int k = 0; k < KNBR; k++) s = fmaf(s_h[k][c], s_xj[k][lane], s);
        __nv_bfloat16 h = __float2bfloat16(s);
        __nv_bfloat16 l = __float2bfloat16(s - __bfloat162float(h));
        Sh[c * INC + lane] = h;
        Sl[c * INC + lane] = l;
    }
    if (t < INC) {
        float m = 0.f;
#pragma unroll
        for (int k = 0; k < KNBR; k++) m += s_xj[k][t];
        g_xjm[br][n * INC + t] = m * (1.0f / 9.0f);
    }
}

// ================= transpose + split W2 -> Wt hi/lo [o][k] =====================
__global__ __launch_bounds__(256) void transposeW_kernel(
    const float* __restrict__ w2g, const float* __restrict__ w2f) {
    int kt = blockIdx.x, br = blockIdx.y;
    const float* W = br ? w2f : w2g;
    __shared__ float tile[64][65];
    int t = threadIdx.x;
    for (int v = t; v < 64 * 64; v += 256) {
        int kk = v >> 6, o = v & 63;
        tile[kk][o] = W[(size_t)(kt * 64 + kk) * 64 + o];
    }
    __syncthreads();
    for (int v = t; v < 64 * 64; v += 256) {
        int o = v >> 6, kk = v & 63;
        float f = tile[kk][o];
        __nv_bfloat16 h = __float2bfloat16(f);
        __nv_bfloat16 l = __float2bfloat16(f - __bfloat162float(h));
        g_Wth[br][(size_t)o * SDIM + kt * 64 + kk] = h;
        g_Wtl[br][(size_t)o * SDIM + kt * 64 + kk] = l;
    }
}

// ================= GEMM via mma.sync bf16 (hi/lo 3-term) =======================
__device__ __forceinline__ void mma_bf16(float* c, const uint32_t* a, const uint32_t* b) {
    asm volatile(
        "mma.sync.aligned.m16n8k16.row.col.f32.bf16.bf16.f32 "
        "{%0,%1,%2,%3}, {%4,%5,%6,%7}, {%8,%9}, {%0,%1,%2,%3};"
        : "+f"(c[0]), "+f"(c[1]), "+f"(c[2]), "+f"(c[3])
        : "r"(a[0]), "r"(a[1]), "r"(a[2]), "r"(a[3]), "r"(b[0]), "r"(b[1]));
}

#define GSMEM_BYTES ((128 * AST * 2 + 64 * AST * 2) * 2)   // 55296 B

__global__ __launch_bounds__(256) void gemm_kernel() {
    extern __shared__ __align__(16) __nv_bfloat16 sm[];
    __nv_bfloat16* Ah = sm;                  // 128 x AST
    __nv_bfloat16* Al = Ah + 128 * AST;
    __nv_bfloat16* Bh = Al + 128 * AST;      // 64 x AST
    __nv_bfloat16* Bl = Bh + 64 * AST;

    int tid = threadIdx.x, warp = tid >> 5, lane = tid & 31;
    int br = blockIdx.y, kz = blockIdx.z;
    int n0 = blockIdx.x * 128;
    int kbase = kz * KLEN;
    int mw = warp >> 1, nw = warp & 1;       // warp tile: m32 x n32
    int g = lane >> 2, t = lane & 3;

    const __nv_bfloat16* ShG = g_Sh[br];
    const __nv_bfloat16* SlG = g_Sl[br];
    const __nv_bfloat16* WhG = g_Wth[br];
    const __nv_bfloat16* WlG = g_Wtl[br];

    float acc[2][4][4];
#pragma unroll
    for (int mi = 0; mi < 2; mi++)
#pragma unroll
        for (int ni = 0; ni < 4; ni++)
#pragma unroll
            for (int e = 0; e < 4; e++) acc[mi][ni][e] = 0.f;

    for (int c = 0; c < KLEN / KC; c++) {
        int koff = kbase + c * KC;
        __syncthreads();
#pragma unroll
        for (int u = tid; u < 1024; u += 256) {
            int m = u >> 3, j = u & 7;
            size_t s = (size_t)(n0 + m) * SDIM + koff + j * 8;
            *reinterpret_cast<uint4*>(&Ah[m * AST + j * 8]) =
                *reinterpret_cast<const uint4*>(&ShG[s]);
            *reinterpret_cast<uint4*>(&Al[m * AST + j * 8]) =
                *reinterpret_cast<const uint4*>(&SlG[s]);
        }
#pragma unroll
        for (int u = tid; u < 512; u += 256) {
            int o = u >> 3, j = u & 7;
            size_t s = (size_t)o * SDIM + koff + j * 8;
            *reinterpret_cast<uint4*>(&Bh[o * AST + j * 8]) =
                *reinterpret_cast<const uint4*>(&WhG[s]);
            *reinterpret_cast<uint4*>(&Bl[o * AST + j * 8]) =
                *reinterpret_cast<const uint4*>(&WlG[s]);
        }
        __syncthreads();

#pragma unroll
        for (int ks = 0; ks < KC / 16; ks++) {
            int k0 = ks * 16;
            uint32_t ah[2][4], al[2][4], bh[4][2], bl[4][2];
#pragma unroll
            for (int mi = 0; mi < 2; mi++) {
                int r0 = mw * 32 + mi * 16;
                ah[mi][0] = *reinterpret_cast<const uint32_t*>(&Ah[(r0 + g) * AST + k0 + 2 * t]);
                ah[mi][1] = *reinterpret_cast<const uint32_t*>(&Ah[(r0 + g + 8) * AST + k0 + 2 * t]);
                ah[mi][2] = *reinterpret_cast<const uint32_t*>(&Ah[(r0 + g) * AST + k0 + 2 * t + 8]);
                ah[mi][3] = *reinterpret_cast<const uint32_t*>(&Ah[(r0 + g + 8) * AST + k0 + 2 * t + 8]);
                al[mi][0] = *reinterpret_cast<const uint32_t*>(&Al[(r0 + g) * AST + k0 + 2 * t]);
                al[mi][1] = *reinterpret_cast<const uint32_t*>(&Al[(r0 + g + 8) * AST + k0 + 2 * t]);
                al[mi][2] = *reinterpret_cast<const uint32_t*>(&Al[(r0 + g) * AST + k0 + 2 * t + 8]);
                al[mi][3] = *reinterpret_cast<const uint32_t*>(&Al[(r0 + g + 8) * AST + k0 + 2 * t + 8]);
            }
#pragma unroll
            for (int ni = 0; ni < 4; ni++) {
                int o0 = nw * 32 + ni * 8;
                bh[ni][0] = *reinterpret_cast<const uint32_t*>(&Bh[(o0 + g) * AST + k0 + 2 * t]);
                bh[ni][1] = *reinterpret_cast<const uint32_t*>(&Bh[(o0 + g) * AST + k0 + 2 * t + 8]);
                bl[ni][0] = *reinterpret_cast<const uint32_t*>(&Bl[(o0 + g) * AST + k0 + 2 * t]);
                bl[ni][1] = *reinterpret_cast<const uint32_t*>(&Bl[(o0 + g) * AST + k0 + 2 * t + 8]);
            }
#pragma unroll
            for (int mi = 0; mi < 2; mi++)
#pragma unroll
                for (int ni = 0; ni < 4; ni++) {
                    mma_bf16(acc[mi][ni], ah[mi], bh[ni]);
                    mma_bf16(acc[mi][ni], ah[mi], bl[ni]);
                    mma_bf16(acc[mi][ni], al[mi], bh[ni]);
                }
        }
    }

    float* P = &g_part[br][kz][0][0];
#pragma unroll
    for (int mi = 0; mi < 2; mi++) {
        int r0 = mw * 32 + mi * 16;
#pragma unroll
        for (int ni = 0; ni < 4; ni++) {
            int col = nw * 32 + ni * 8 + 2 * t;
            float2 v01 = make_float2(acc[mi][ni][0], acc[mi][ni][1]);
            float2 v23 = make_float2(acc[mi][ni][2], acc[mi][ni][3]);
            *reinterpret_cast<float2*>(&P[(size_t)(n0 + r0 + g) * OUTC + col]) = v01;
            *reinterpret_cast<float2*>(&P[(size_t)(n0 + r0 + g + 8) * OUTC + col]) = v23;
        }
    }
}

// ================= combine: out = 0.5*((sum parts)/9 + xm@b2 both) =============
__global__ __launch_bounds__(256) void combine_kernel(
    const float* __restrict__ b2g, const float* __restrict__ b2f,
    float* __restrict__ out) {
    __shared__ float s_b2[2][INC * OUTC];
    __shared__ float s_xm[2][4][INC];

    int tid = threadIdx.x;
    int nl = tid >> 6, o = tid & 63;
    int n = blockIdx.x * 4 + nl;

    for (int v = tid; v < INC * OUTC; v += 256) {
        s_b2[0][v] = b2g[v];
        s_b2[1][v] = b2f[v];
    }
    {
        int br = tid >> 7, nn = (tid >> 5) & 3, i = tid & 31;
        s_xm[br][nn][i] = g_xjm[br][(size_t)(blockIdx.x * 4 + nn) * INC + i];
    }
    __syncthreads();

    float val = 0.f;
#pragma unroll
    for (int br = 0; br < 2; br++)
#pragma unroll
        for (int kzi = 0; kzi < KSPL; kzi++)
            val += g_part[br][kzi][n][o];
    val *= (1.0f / 9.0f);
#pragma unroll
    for (int br = 0; br < 2; br++)
#pragma unroll
        for (int i = 0; i < INC; i++)
            val = fmaf(s_xm[br][nl][i], s_b2[br][i * OUTC + o], val);
    out[(size_t)n * OUTC + o] = 0.5f * val;
}

// ---------------- launch -------------------------------------------------------
extern "C" void kernel_launch(void* const* d_in, const int* in_sizes, int n_in,
                              void* d_out, int out_size) {
    const float* x   = (const float*)d_in[0];
    const float* pos = (const float*)d_in[1];
    const float* w1g = (const float*)d_in[2];
    const float* b1g = (const float*)d_in[3];
    const float* w2g = (const float*)d_in[4];
    const float* b2g = (const float*)d_in[5];
    const float* w1f = (const float*)d_in[6];
    const float* b1f = (const float*)d_in[7];
    const float* w2f = (const float*)d_in[8];
    const float* b2f = (const float*)d_in[9];
    float* out = (float*)d_out;

    cudaFuncSetAttribute(gemm_kernel, cudaFuncAttributeMaxDynamicSharedMemorySize,
                         GSMEM_BYTES);

    knn_pos_kernel<<<dim3(NND / 8, 2), 256>>>(pos);                   // 0
    knn_mergeP_kernel<0, 2><<<NND / 256, 256>>>();                    // 1
    buildS_kernel<<<NND, 128>>>(x, pos, w1g, b1g, 0);                 // 2
    knn_feat_kernel<<<dim3(NND / 16, 4), 256>>>(x);                   // 3  <- profiled
    knn_mergeP_kernel<1, 4><<<NND / 256, 256>>>();                    // 4
    buildS_kernel<<<NND, 128>>>(x, pos, w1f, b1f, 1);                 // 5
    transposeW_kernel<<<dim3(SDIM / 64, 2), 256>>>(w2g, w2f);         // 6
    gemm_kernel<<<dim3(NND / 128, 2, KSPL), 256, GSMEM_BYTES>>>();    // 7
    combine_kernel<<<NND / 4, 256>>>(b2g, b2f, out);                  // 8
}

// round 8
// speedup vs baseline: 1.6019x; 1.1806x over previous
#include <cuda_runtime.h>
#include <cuda_bf16.h>
#include <math.h>
#include <string.h>
#include <stdint.h>

#define NND   4096
#define KNBR  9
#define INC   32
#define OUTC  64
#define HID   128
#define SDIM  4096
#define KSPL  4
#define KLEN  (SDIM / KSPL)   // 1024
#define KC    64
#define AST   72              // smem row stride (bf16) -> conflict-free frags

// ---------------- scratch (static device globals; no allocation) ----------------
__device__ int   g_idx[2][NND * KNBR];
__device__ float g_pd[2][4][NND][KNBR];
__device__ int   g_pi[2][4][NND][KNBR];
__device__ __nv_bfloat16 g_Sh[2][(size_t)NND * SDIM];   // 32 MB
__device__ __nv_bfloat16 g_Sl[2][(size_t)NND * SDIM];   // 32 MB
__device__ __nv_bfloat16 g_Wth[2][OUTC * SDIM];         // W^T hi [o][k]
__device__ __nv_bfloat16 g_Wtl[2][OUTC * SDIM];         // W^T lo [o][k]
__device__ float g_xjm[2][NND * INC];
__device__ float g_part[2][KSPL][NND][OUTC];

// ======================= KNN helpers ===========================================
__device__ __forceinline__ bool knn_less(float d, int i, float d2, int i2) {
    return (d < d2) || (d == d2 && i < i2);
}
__device__ __forceinline__ void knn_insert(float dist, int j, float bd[KNBR], int bi[KNBR]) {
    if (knn_less(dist, j, bd[KNBR - 1], bi[KNBR - 1])) {
        float cd = dist; int ci = j;
#pragma unroll
        for (int r = 0; r < KNBR; r++) {
            bool sw = knn_less(cd, ci, bd[r], bi[r]);
            float td = bd[r]; int ti = bi[r];
            if (sw) { bd[r] = cd; bi[r] = ci; cd = td; ci = ti; }
        }
    }
}
__device__ __forceinline__ void knn_merge_warp(float* md, int* mi, const float bd[KNBR],
                                               const int bi[KNBR], int lane,
                                               float* opd, int* opi, int q) {
#pragma unroll
    for (int r = 0; r < KNBR; r++) { md[lane * KNBR + r] = bd[r]; mi[lane * KNBR + r] = bi[r]; }
    __syncwarp();
    int p = 0;
    for (int r = 0; r < KNBR; r++) {
        float cd = (p < KNBR) ? md[lane * KNBR + p] : 3.4e38f;
        int   ci = (p < KNBR) ? mi[lane * KNBR + p] : 0x7FFFFFFF;
        float rd = cd; int ri = ci;
#pragma unroll
        for (int off = 16; off; off >>= 1) {
            float od = __shfl_xor_sync(0xFFFFFFFFu, rd, off);
            int   oi = __shfl_xor_sync(0xFFFFFFFFu, ri, off);
            if (knn_less(od, oi, rd, ri)) { rd = od; ri = oi; }
        }
        if (ci == ri && p < KNBR) p++;
        if (lane == 0) { opd[q * KNBR + r] = rd; opi[q * KNBR + r] = ri; }
    }
    __syncwarp();
}

// ---------------- KNN on pos: part-split, 4 candidates in flight per lane -------
#define PPART (NND / 2)
__global__ __launch_bounds__(256) void knn_pos_kernel(const float* __restrict__ pos) {
    __shared__ float smem[PPART * 3];
    int t = threadIdx.x, w = t >> 5, lane = t & 31;
    int q = blockIdx.x * 8 + w;
    int part = blockIdx.y;
    int base = part * PPART;

    for (int v = t; v < PPART * 3; v += 256) smem[v] = pos[base * 3 + v];
    __syncthreads();

    float q0 = pos[q * 3 + 0], q1 = pos[q * 3 + 1], q2 = pos[q * 3 + 2];
    float sqq = 0.f;
    sqq = fmaf(q0, q0, sqq); sqq = fmaf(q1, q1, sqq); sqq = fmaf(q2, q2, sqq);

    float bd[KNBR]; int bi[KNBR];
#pragma unroll
    for (int r = 0; r < KNBR; r++) { bd[r] = 3.4e38f; bi[r] = 0x7FFFFFFF; }

    for (int jl = lane; jl < PPART; jl += 128) {
        float dist[4];
#pragma unroll
        for (int u = 0; u < 4; u++) {
            int jj = jl + u * 32;
            float c0 = smem[jj * 3 + 0], c1 = smem[jj * 3 + 1], c2 = smem[jj * 3 + 2];
            float acc = 0.f;
            acc = fmaf(q0, c0, acc); acc = fmaf(q1, c1, acc); acc = fmaf(q2, c2, acc);
            float sqj = 0.f;
            sqj = fmaf(c0, c0, sqj); sqj = fmaf(c1, c1, sqj); sqj = fmaf(c2, c2, sqj);
            dist[u] = (sqq + sqj) - 2.0f * acc;
        }
#pragma unroll
        for (int u = 0; u < 4; u++) knn_insert(dist[u], base + jl + u * 32, bd, bi);
    }
    __syncthreads();

    float* md = smem + (size_t)w * 288;
    int*   mi = (int*)(smem + 8 * 288) + (size_t)w * 288;
    knn_merge_warp(md, mi, bd, bi, lane, &g_pd[0][part][0][0], &g_pi[0][part][0][0], q);
}

// ---------------- KNN on x: two-phase tile kernel ------------------------------
// Block: 32 queries, part of candidate range (2 parts). Phase A computes the
// 32x128 distance tile into smem (GEMM-style, 2q x 8c per thread); Phase B does
// top-9 selection with 8 lanes per query; exact 8-lane merge at the end.
#define CT 128
#define FPART2 (NND / 2)
__global__ __launch_bounds__(256) void knn_feat_kernel(const float* __restrict__ x) {
    __shared__ float s_qT[32][36];    // [k][q]
    __shared__ float s_cT[32][132];   // [k][c]
    __shared__ float s_D[32][136];    // [q][c]
    __shared__ float s_sqq[32];
    __shared__ float s_sqc[CT];

    int tid = threadIdx.x, lane = tid & 31;
    int q0 = blockIdx.x * 32;
    int part = blockIdx.y;
    int base0 = part * FPART2;
    int ty = tid >> 4, tx = tid & 15;            // 2 queries x 8 candidates
    int qi = ((tid >> 5) << 2) + (lane >> 3);    // phase-B query (4 per warp)
    int sub = lane & 7;                          // phase-B lane-in-group

    // stage queries k-major (coalesced gmem read)
    for (int v = tid; v < 1024; v += 256) {
        int k = v & 31, q = v >> 5;
        s_qT[k][q] = x[(size_t)(q0 + q) * INC + k];
    }
    __syncthreads();
    if (tid < 32) {   // query norms: sequential chain == dot chain below
        float s = 0.f;
#pragma unroll
        for (int k = 0; k < 32; k++) { float v = s_qT[k][tid]; s = fmaf(v, v, s); }
        s_sqq[tid] = s;
    }

    float bd[KNBR]; int bi[KNBR];
#pragma unroll
    for (int r = 0; r < KNBR; r++) { bd[r] = 3.4e38f; bi[r] = 0x7FFFFFFF; }

    for (int tile = 0; tile < FPART2 / CT; tile++) {
        int base = base0 + tile * CT;
        __syncthreads();
        // stage candidate tile k-major
        for (int v = tid; v < CT * 32; v += 256) {
            int k = v & 31, c = v >> 5;
            s_cT[k][c] = x[(size_t)(base + c) * INC + k];
        }
        __syncthreads();
        if (tid < CT) {   // candidate norms: same sequential chain
            float s = 0.f;
#pragma unroll
            for (int k = 0; k < 32; k++) { float v = s_cT[k][tid]; s = fmaf(v, v, s); }
            s_sqc[tid] = s;
        }
        __syncthreads();

        // Phase A: 16 independent dot chains per thread
        float acc[2][8];
#pragma unroll
        for (int e = 0; e < 2; e++)
#pragma unroll
            for (int j = 0; j < 8; j++) acc[e][j] = 0.f;
#pragma unroll
        for (int k = 0; k < 32; k++) {
            float qv0 = s_qT[k][2 * ty + 0];
            float qv1 = s_qT[k][2 * ty + 1];
            float4 ca = *reinterpret_cast<const float4*>(&s_cT[k][8 * tx]);
            float4 cb = *reinterpret_cast<const float4*>(&s_cT[k][8 * tx + 4]);
            acc[0][0] = fmaf(qv0, ca.x, acc[0][0]); acc[0][1] = fmaf(qv0, ca.y, acc[0][1]);
            acc[0][2] = fmaf(qv0, ca.z, acc[0][2]); acc[0][3] = fmaf(qv0, ca.w, acc[0][3]);
            acc[0][4] = fmaf(qv0, cb.x, acc[0][4]); acc[0][5] = fmaf(qv0, cb.y, acc[0][5]);
            acc[0][6] = fmaf(qv0, cb.z, acc[0][6]); acc[0][7] = fmaf(qv0, cb.w, acc[0][7]);
            acc[1][0] = fmaf(qv1, ca.x, acc[1][0]); acc[1][1] = fmaf(qv1, ca.y, acc[1][1]);
            acc[1][2] = fmaf(qv1, ca.z, acc[1][2]); acc[1][3] = fmaf(qv1, ca.w, acc[1][3]);
            acc[1][4] = fmaf(qv1, cb.x, acc[1][4]); acc[1][5] = fmaf(qv1, cb.y, acc[1][5]);
            acc[1][6] = fmaf(qv1, cb.z, acc[1][6]); acc[1][7] = fmaf(qv1, cb.w, acc[1][7]);
        }
        // dist = sqq + sqc - 2*dot ; float4 stores (conflict-light)
#pragma unroll
        for (int e = 0; e < 2; e++) {
            float sq = s_sqq[2 * ty + e];
            float4 d0 = make_float4((sq + s_sqc[8 * tx + 0]) - 2.0f * acc[e][0],
                                    (sq + s_sqc[8 * tx + 1]) - 2.0f * acc[e][1],
                                    (sq + s_sqc[8 * tx + 2]) - 2.0f * acc[e][2],
                                    (sq + s_sqc[8 * tx + 3]) - 2.0f * acc[e][3]);
            float4 d1 = make_float4((sq + s_sqc[8 * tx + 4]) - 2.0f * acc[e][4],
                                    (sq + s_sqc[8 * tx + 5]) - 2.0f * acc[e][5],
                                    (sq + s_sqc[8 * tx + 6]) - 2.0f * acc[e][6],
                                    (sq + s_sqc[8 * tx + 7]) - 2.0f * acc[e][7]);
            *reinterpret_cast<float4*>(&s_D[2 * ty + e][8 * tx]) = d0;
            *reinterpret_cast<float4*>(&s_D[2 * ty + e][8 * tx + 4]) = d1;
        }
        __syncthreads();

        // Phase B: 8 lanes per query, disjoint candidate subsets
#pragma unroll
        for (int t2 = 0; t2 < CT / 8; t2++) {
            int c = t2 * 8 + sub;
            knn_insert(s_D[qi][c], base + c, bd, bi);
        }
    }
    __syncthreads();   // done with s_cT / s_D; overlay merge buffers

    // exact 8-lane merge per query
    float* md = reinterpret_cast<float*>(s_cT);
    int*   mi = reinterpret_cast<int*>(s_D);
#pragma unroll
    for (int r = 0; r < KNBR; r++) { md[tid * KNBR + r] = bd[r]; mi[tid * KNBR + r] = bi[r]; }
    __syncwarp();
    int p = 0;
    for (int r = 0; r < KNBR; r++) {
        float cd = (p < KNBR) ? md[tid * KNBR + p] : 3.4e38f;
        int   ci = (p < KNBR) ? mi[tid * KNBR + p] : 0x7FFFFFFF;
        float rd = cd; int ri = ci;
#pragma unroll
        for (int off = 4; off; off >>= 1) {
            float od = __shfl_xor_sync(0xFFFFFFFFu, rd, off);
            int   oi = __shfl_xor_sync(0xFFFFFFFFu, ri, off);
            if (knn_less(od, oi, rd, ri)) { rd = od; ri = oi; }
        }
        if (ci == ri && p < KNBR) p++;   // candidate subsets disjoint per lane
        if (sub == 0) {
            g_pd[1][part][q0 + qi][r] = rd;
            g_pi[1][part][q0 + qi][r] = ri;
        }
    }
}

template <int BR, int P>
__global__ __launch_bounds__(256) void knn_mergeP_kernel() {
    int q = blockIdx.x * 256 + threadIdx.x;
    int p[4] = {0, 0, 0, 0};
    for (int r = 0; r < KNBR; r++) {
        float bd = 3.4e38f; int bi = 0x7FFFFFFF, bt = 0;
#pragma unroll
        for (int t = 0; t < P; t++) {
            float d = g_pd[BR][t][q][p[t]];
            int   i = g_pi[BR][t][q][p[t]];
            if (knn_less(d, i, bd, bi)) { bd = d; bi = i; bt = t; }
        }
        p[bt]++;
        g_idx[BR][q * KNBR + r] = bi;
    }
}

// ================= buildS: attrs -> h -> S (bf16 hi/lo), xjmean =================
__global__ __launch_bounds__(128) void buildS_kernel(
    const float* __restrict__ x, const float* __restrict__ pos,
    const float* __restrict__ w1, const float* __restrict__ b1, int br) {
    int n = blockIdx.x;
    int t = threadIdx.x;

    __shared__ int   s_idx[KNBR];
    __shared__ float s_xj[KNBR][INC];
    __shared__ float s_attr[KNBR][3];
    __shared__ float s_h[KNBR][HID];
    __shared__ float s_pn[3];

    const int* idx = g_idx[br];

    if (t < KNBR) s_idx[t] = idx[n * KNBR + t];
    if (t < 3)    s_pn[t] = pos[n * 3 + t];
    __syncthreads();

    for (int v = t; v < KNBR * INC; v += 128)
        s_xj[v / INC][v % INC] = x[(size_t)s_idx[v / INC] * INC + (v % INC)];

    if (t < KNBR) {
        int sj = s_idx[t];
        float cx = pos[sj * 3 + 0] - s_pn[0];
        float cy = pos[sj * 3 + 1] - s_pn[1];
        float cz = pos[sj * 3 + 2] - s_pn[2];
        float rho = sqrtf((cx * cx + cy * cy) + cz * cz);
        float th  = atan2f(cy, cx);
        float ratio = cz / fmaxf(rho, 1e-12f);
        ratio = fminf(1.0f, fmaxf(-1.0f, ratio));
        float ph = acosf(ratio);
        s_attr[t][0] = rho; s_attr[t][1] = th; s_attr[t][2] = ph;
    }
    __syncthreads();

    {
        int c = t;
        float wa = w1[c], wb = w1[HID + c], wc = w1[2 * HID + c], bb = b1[c];
        float hk[KNBR];
#pragma unroll
        for (int k = 0; k < KNBR; k++)
            hk[k] = tanhf(bb + s_attr[k][0] * wa + s_attr[k][1] * wb + s_attr[k][2] * wc);
#pragma unroll
        for (int k = 0; k < KNBR; k++) s_h[k][c] = hk[k];
    }
    __syncthreads();

    int w = t >> 5, lane = t & 31;
    __nv_bfloat16* Sh = g_Sh[br] + (size_t)n * SDIM;
    __nv_bfloat16* Sl = g_Sl[br] + (size_t)n * SDIM;
    for (int j = 0; j < 32; j++) {
        int c = w * 32 + j;
        float s = 0.f;
#pragma unroll
        for (int k = 0; k < KNBR; k++) s = fmaf(s_h[k][c], s_xj[k][lane], s);
        __nv_bfloat16 h = __float2bfloat16(s);
        __nv_bfloat16 l = __float2bfloat16(s - __bfloat162float(h));
        Sh[c * INC + lane] = h;
        Sl[c * INC + lane] = l;
    }
    if (t < INC) {
        float m = 0.f;
#pragma unroll
        for (int k = 0; k < KNBR; k++) m += s_xj[k][t];
        g_xjm[br][n * INC + t] = m * (1.0f / 9.0f);
    }
}

// ================= transpose + split W2 -> Wt hi/lo [o][k] =====================
__global__ __launch_bounds__(256) void transposeW_kernel(
    const float* __restrict__ w2g, const float* __restrict__ w2f) {
    int kt = blockIdx.x, br = blockIdx.y;
    const float* W = br ? w2f : w2g;
    __shared__ float tile[64][65];
    int t = threadIdx.x;
    for (int v = t; v < 64 * 64; v += 256) {
        int kk = v >> 6, o = v & 63;
        tile[kk][o] = W[(size_t)(kt * 64 + kk) * 64 + o];
    }
    __syncthreads();
    for (int v = t; v < 64 * 64; v += 256) {
        int o = v >> 6, kk = v & 63;
        float f = tile[kk][o];
        __nv_bfloat16 h = __float2bfloat16(f);
        __nv_bfloat16 l = __float2bfloat16(f - __bfloat162float(h));
        g_Wth[br][(size_t)o * SDIM + kt * 64 + kk] = h;
        g_Wtl[br][(size_t)o * SDIM + kt * 64 + kk] = l;
    }
}

// ================= GEMM via mma.sync bf16 (hi/lo 3-term) =======================
__device__ __forceinline__ void mma_bf16(float* c, const uint32_t* a, const uint32_t* b) {
    asm volatile(
        "mma.sync.aligned.m16n8k16.row.col.f32.bf16.bf16.f32 "
        "{%0,%1,%2,%3}, {%4,%5,%6,%7}, {%8,%9}, {%0,%1,%2,%3};"
        : "+f"(c[0]), "+f"(c[1]), "+f"(c[2]), "+f"(c[3])
        : "r"(a[0]), "r"(a[1]), "r"(a[2]), "r"(a[3]), "r"(b[0]), "r"(b[1]));
}

#define GSMEM_BYTES ((128 * AST * 2 + 64 * AST * 2) * 2)   // 55296 B

__global__ __launch_bounds__(256) void gemm_kernel() {
    extern __shared__ __align__(16) __nv_bfloat16 sm[];
    __nv_bfloat16* Ah = sm;                  // 128 x AST
    __nv_bfloat16* Al = Ah + 128 * AST;
    __nv_bfloat16* Bh = Al + 128 * AST;      // 64 x AST
    __nv_bfloat16* Bl = Bh + 64 * AST;

    int tid = threadIdx.x, warp = tid >> 5, lane = tid & 31;
    int br = blockIdx.y, kz = blockIdx.z;
    int n0 = blockIdx.x * 128;
    int kbase = kz * KLEN;
    int mw = warp >> 1, nw = warp & 1;       // warp tile: m32 x n32
    int g = lane >> 2, t = lane & 3;

    const __nv_bfloat16* ShG = g_Sh[br];
    const __nv_bfloat16* SlG = g_Sl[br];
    const __nv_bfloat16* WhG = g_Wth[br];
    const __nv_bfloat16* WlG = g_Wtl[br];

    float acc[2][4][4];
#pragma unroll
    for (int mi = 0; mi < 2; mi++)
#pragma unroll
        for (int ni = 0; ni < 4; ni++)
#pragma unroll
            for (int e = 0; e < 4; e++) acc[mi][ni][e] = 0.f;

    for (int c = 0; c < KLEN / KC; c++) {
        int koff = kbase + c * KC;
        __syncthreads();
#pragma unroll
        for (int u = tid; u < 1024; u += 256) {
            int m = u >> 3, j = u & 7;
            size_t s = (size_t)(n0 + m) * SDIM + koff + j * 8;
            *reinterpret_cast<uint4*>(&Ah[m * AST + j * 8]) =
                *reinterpret_cast<const uint4*>(&ShG[s]);
            *reinterpret_cast<uint4*>(&Al[m * AST + j * 8]) =
                *reinterpret_cast<const uint4*>(&SlG[s]);
        }
#pragma unroll
        for (int u = tid; u < 512; u += 256) {
            int o = u >> 3, j = u & 7;
            size_t s = (size_t)o * SDIM + koff + j * 8;
            *reinterpret_cast<uint4*>(&Bh[o * AST + j * 8]) =
                *reinterpret_cast<const uint4*>(&WhG[s]);
            *reinterpret_cast<uint4*>(&Bl[o * AST + j * 8]) =
                *reinterpret_cast<const uint4*>(&WlG[s]);
        }
        __syncthreads();

#pragma unroll
        for (int ks = 0; ks < KC / 16; ks++) {
            int k0 = ks * 16;
            uint32_t ah[2][4], al[2][4], bh[4][2], bl[4][2];
#pragma unroll
            for (int mi = 0; mi < 2; mi++) {
                int r0 = mw * 32 + mi * 16;
                ah[mi][0] = *reinterpret_cast<const uint32_t*>(&Ah[(r0 + g) * AST + k0 + 2 * t]);
                ah[mi][1] = *reinterpret_cast<const uint32_t*>(&Ah[(r0 + g + 8) * AST + k0 + 2 * t]);
                ah[mi][2] = *reinterpret_cast<const uint32_t*>(&Ah[(r0 + g) * AST + k0 + 2 * t + 8]);
                ah[mi][3] = *reinterpret_cast<const uint32_t*>(&Ah[(r0 + g + 8) * AST + k0 + 2 * t + 8]);
                al[mi][0] = *reinterpret_cast<const uint32_t*>(&Al[(r0 + g) * AST + k0 + 2 * t]);
                al[mi][1] = *reinterpret_cast<const uint32_t*>(&Al[(r0 + g + 8) * AST + k0 + 2 * t]);
                al[mi][2] = *reinterpret_cast<const uint32_t*>(&Al[(r0 + g) * AST + k0 + 2 * t + 8]);
                al[mi][3] = *reinterpret_cast<const uint32_t*>(&Al[(r0 + g + 8) * AST + k0 + 2 * t + 8]);
            }
#pragma unroll
            for (int ni = 0; ni < 4; ni++) {
                int o0 = nw * 32 + ni * 8;
                bh[ni][0] = *reinterpret_cast<const uint32_t*>(&Bh[(o0 + g) * AST + k0 + 2 * t]);
                bh[ni][1] = *reinterpret_cast<const uint32_t*>(&Bh[(o0 + g) * AST + k0 + 2 * t + 8]);
                bl[ni][0] = *reinterpret_cast<const uint32_t*>(&Bl[(o0 + g) * AST + k0 + 2 * t]);
                bl[ni][1] = *reinterpret_cast<const uint32_t*>(&Bl[(o0 + g) * AST + k0 + 2 * t + 8]);
            }
#pragma unroll
            for (int mi = 0; mi < 2; mi++)
#pragma unroll
                for (int ni = 0; ni < 4; ni++) {
                    mma_bf16(acc[mi][ni], ah[mi], bh[ni]);
                    mma_bf16(acc[mi][ni], ah[mi], bl[ni]);
                    mma_bf16(acc[mi][ni], al[mi], bh[ni]);
                }
        }
    }

    float* P = &g_part[br][kz][0][0];
#pragma unroll
    for (int mi = 0; mi < 2; mi++) {
        int r0 = mw * 32 + mi * 16;
#pragma unroll
        for (int ni = 0; ni < 4; ni++) {
            int col = nw * 32 + ni * 8 + 2 * t;
            float2 v01 = make_float2(acc[mi][ni][0], acc[mi][ni][1]);
            float2 v23 = make_float2(acc[mi][ni][2], acc[mi][ni][3]);
            *reinterpret_cast<float2*>(&P[(size_t)(n0 + r0 + g) * OUTC + col]) = v01;
            *reinterpret_cast<float2*>(&P[(size_t)(n0 + r0 + g + 8) * OUTC + col]) = v23;
        }
    }
}

// ================= combine: out = 0.5*((sum parts)/9 + xm@b2 both) =============
__global__ __launch_bounds__(256) void combine_kernel(
    const float* __restrict__ b2g, const float* __restrict__ b2f,
    float* __restrict__ out) {
    __shared__ float s_b2[2][INC * OUTC];
    __shared__ float s_xm[2][4][INC];

    int tid = threadIdx.x;
    int nl = tid >> 6, o = tid & 63;
    int n = blockIdx.x * 4 + nl;

    for (int v = tid; v < INC * OUTC; v += 256) {
        s_b2[0][v] = b2g[v];
        s_b2[1][v] = b2f[v];
    }
    {
        int br = tid >> 7, nn = (tid >> 5) & 3, i = tid & 31;
        s_xm[br][nn][i] = g_xjm[br][(size_t)(blockIdx.x * 4 + nn) * INC + i];
    }
    __syncthreads();

    float val = 0.f;
#pragma unroll
    for (int br = 0; br < 2; br++)
#pragma unroll
        for (int kzi = 0; kzi < KSPL; kzi++)
            val += g_part[br][kzi][n][o];
    val *= (1.0f / 9.0f);
#pragma unroll
    for (int br = 0; br < 2; br++)
#pragma unroll
        for (int i = 0; i < INC; i++)
            val = fmaf(s_xm[br][nl][i], s_b2[br][i * OUTC + o], val);
    out[(size_t)n * OUTC + o] = 0.5f * val;
}

// ---------------- launch -------------------------------------------------------
extern "C" void kernel_launch(void* const* d_in, const int* in_sizes, int n_in,
                              void* d_out, int out_size) {
    const float* x   = (const float*)d_in[0];
    const float* pos = (const float*)d_in[1];
    const float* w1g = (const float*)d_in[2];
    const float* b1g = (const float*)d_in[3];
    const float* w2g = (const float*)d_in[4];
    const float* b2g = (const float*)d_in[5];
    const float* w1f = (const float*)d_in[6];
    const float* b1f = (const float*)d_in[7];
    const float* w2f = (const float*)d_in[8];
    const float* b2f = (const float*)d_in[9];
    float* out = (float*)d_out;

    cudaFuncSetAttribute(gemm_kernel, cudaFuncAttributeMaxDynamicSharedMemorySize,
                         GSMEM_BYTES);

    knn_pos_kernel<<<dim3(NND / 8, 2), 256>>>(pos);                   // 0
    knn_mergeP_kernel<0, 2><<<NND / 256, 256>>>();                    // 1
    buildS_kernel<<<NND, 128>>>(x, pos, w1g, b1g, 0);                 // 2
    knn_feat_kernel<<<dim3(NND / 32, 2), 256>>>(x);                   // 3  <- profiled
    knn_mergeP_kernel<1, 2><<<NND / 256, 256>>>();                    // 4
    buildS_kernel<<<NND, 128>>>(x, pos, w1f, b1f, 1);                 // 5
    transposeW_kernel<<<dim3(SDIM / 64, 2), 256>>>(w2g, w2f);         // 6
    gemm_kernel<<<dim3(NND / 128, 2, KSPL), 256, GSMEM_BYTES>>>();    // 7
    combine_kernel<<<NND / 4, 256>>>(b2g, b2f, out);                  // 8
}

// round 9
// speedup vs baseline: 1.8739x; 1.1698x over previous
#include <cuda_runtime.h>
#include <cuda_bf16.h>
#include <math.h>
#include <string.h>
#include <stdint.h>

#define NND   4096
#define KNBR  9
#define INC   32
#define OUTC  64
#define HID   128
#define SDIM  4096
#define KSPL  4
#define KLEN  (SDIM / KSPL)   // 1024
#define KC    64
#define AST   72              // smem row stride (bf16) -> conflict-free frags

// ---------------- scratch (static device globals; no allocation) ----------------
__device__ int   g_idx[2][NND * KNBR];
__device__ float g_pd[2][8][NND][KNBR];
__device__ int   g_pi[2][8][NND][KNBR];
__device__ __nv_bfloat16 g_Sh[2][(size_t)NND * SDIM];   // 32 MB
__device__ __nv_bfloat16 g_Sl[2][(size_t)NND * SDIM];   // 32 MB
__device__ __nv_bfloat16 g_Wth[2][OUTC * SDIM];         // W^T hi [o][k]
__device__ __nv_bfloat16 g_Wtl[2][OUTC * SDIM];         // W^T lo [o][k]
__device__ float g_xjm[2][NND * INC];
__device__ float g_part[2][KSPL][NND][OUTC];

// ======================= KNN helpers ===========================================
__device__ __forceinline__ bool knn_less(float d, int i, float d2, int i2) {
    return (d < d2) || (d == d2 && i < i2);
}
__device__ __forceinline__ void knn_insert(float dist, int j, float bd[KNBR], int bi[KNBR]) {
    if (knn_less(dist, j, bd[KNBR - 1], bi[KNBR - 1])) {
        float cd = dist; int ci = j;
#pragma unroll
        for (int r = 0; r < KNBR; r++) {
            bool sw = knn_less(cd, ci, bd[r], bi[r]);
            float td = bd[r]; int ti = bi[r];
            if (sw) { bd[r] = cd; bi[r] = ci; cd = td; ci = ti; }
        }
    }
}
__device__ __forceinline__ void knn_merge_warp(float* md, int* mi, const float bd[KNBR],
                                               const int bi[KNBR], int lane,
                                               float* opd, int* opi, int q) {
#pragma unroll
    for (int r = 0; r < KNBR; r++) { md[lane * KNBR + r] = bd[r]; mi[lane * KNBR + r] = bi[r]; }
    __syncwarp();
    int p = 0;
    for (int r = 0; r < KNBR; r++) {
        float cd = (p < KNBR) ? md[lane * KNBR + p] : 3.4e38f;
        int   ci = (p < KNBR) ? mi[lane * KNBR + p] : 0x7FFFFFFF;
        float rd = cd; int ri = ci;
#pragma unroll
        for (int off = 16; off; off >>= 1) {
            float od = __shfl_xor_sync(0xFFFFFFFFu, rd, off);
            int   oi = __shfl_xor_sync(0xFFFFFFFFu, ri, off);
            if (knn_less(od, oi, rd, ri)) { rd = od; ri = oi; }
        }
        if (ci == ri && p < KNBR) p++;
        if (lane == 0) { opd[q * KNBR + r] = rd; opi[q * KNBR + r] = ri; }
    }
    __syncwarp();
}

// ---------------- KNN on pos: part-split, 4 candidates in flight per lane -------
#define PPART (NND / 2)
__global__ __launch_bounds__(256) void knn_pos_kernel(const float* __restrict__ pos) {
    __shared__ float smem[PPART * 3];
    int t = threadIdx.x, w = t >> 5, lane = t & 31;
    int q = blockIdx.x * 8 + w;
    int part = blockIdx.y;
    int base = part * PPART;

    for (int v = t; v < PPART * 3; v += 256) smem[v] = pos[base * 3 + v];
    __syncthreads();

    float q0 = pos[q * 3 + 0], q1 = pos[q * 3 + 1], q2 = pos[q * 3 + 2];
    float sqq = 0.f;
    sqq = fmaf(q0, q0, sqq); sqq = fmaf(q1, q1, sqq); sqq = fmaf(q2, q2, sqq);

    float bd[KNBR]; int bi[KNBR];
#pragma unroll
    for (int r = 0; r < KNBR; r++) { bd[r] = 3.4e38f; bi[r] = 0x7FFFFFFF; }

    for (int jl = lane; jl < PPART; jl += 128) {
        float dist[4];
#pragma unroll
        for (int u = 0; u < 4; u++) {
            int jj = jl + u * 32;
            float c0 = smem[jj * 3 + 0], c1 = smem[jj * 3 + 1], c2 = smem[jj * 3 + 2];
            float acc = 0.f;
            acc = fmaf(q0, c0, acc); acc = fmaf(q1, c1, acc); acc = fmaf(q2, c2, acc);
            float sqj = 0.f;
            sqj = fmaf(c0, c0, sqj); sqj = fmaf(c1, c1, sqj); sqj = fmaf(c2, c2, sqj);
            dist[u] = (sqq + sqj) - 2.0f * acc;
        }
#pragma unroll
        for (int u = 0; u < 4; u++) knn_insert(dist[u], base + jl + u * 32, bd, bi);
    }
    __syncthreads();

    float* md = smem + (size_t)w * 288;
    int*   mi = (int*)(smem + 8 * 288) + (size_t)w * 288;
    knn_merge_warp(md, mi, bd, bi, lane, &g_pd[0][part][0][0], &g_pi[0][part][0][0], q);
}

// ---------------- KNN on x: two-phase tile kernel, 8 candidate parts ------------
#define CT 128
#define FPART2 (NND / 8)
__global__ __launch_bounds__(256) void knn_feat_kernel(const float* __restrict__ x) {
    __shared__ float s_qT[32][36];    // [k][q]
    __shared__ float s_cT[32][132];   // [k][c]
    __shared__ float s_D[32][136];    // [q][c]
    __shared__ float s_sqq[32];
    __shared__ float s_sqc[CT];

    int tid = threadIdx.x, lane = tid & 31;
    int q0 = blockIdx.x * 32;
    int part = blockIdx.y;
    int base0 = part * FPART2;
    int ty = tid >> 4, tx = tid & 15;            // 2 queries x 8 candidates
    int qi = ((tid >> 5) << 2) + (lane >> 3);    // phase-B query (4 per warp)
    int sub = lane & 7;                          // phase-B lane-in-group

    // stage queries k-major (coalesced gmem read)
    for (int v = tid; v < 1024; v += 256) {
        int k = v & 31, q = v >> 5;
        s_qT[k][q] = x[(size_t)(q0 + q) * INC + k];
    }
    __syncthreads();
    if (tid < 32) {   // query norms: sequential chain == dot chain below
        float s = 0.f;
#pragma unroll
        for (int k = 0; k < 32; k++) { float v = s_qT[k][tid]; s = fmaf(v, v, s); }
        s_sqq[tid] = s;
    }

    float bd[KNBR]; int bi[KNBR];
#pragma unroll
    for (int r = 0; r < KNBR; r++) { bd[r] = 3.4e38f; bi[r] = 0x7FFFFFFF; }

    for (int tile = 0; tile < FPART2 / CT; tile++) {
        int base = base0 + tile * CT;
        __syncthreads();
        // stage candidate tile k-major
        for (int v = tid; v < CT * 32; v += 256) {
            int k = v & 31, c = v >> 5;
            s_cT[k][c] = x[(size_t)(base + c) * INC + k];
        }
        __syncthreads();
        if (tid < CT) {   // candidate norms: same sequential chain
            float s = 0.f;
#pragma unroll
            for (int k = 0; k < 32; k++) { float v = s_cT[k][tid]; s = fmaf(v, v, s); }
            s_sqc[tid] = s;
        }
        __syncthreads();

        // Phase A: 16 independent dot chains per thread
        float acc[2][8];
#pragma unroll
        for (int e = 0; e < 2; e++)
#pragma unroll
            for (int j = 0; j < 8; j++) acc[e][j] = 0.f;
#pragma unroll
        for (int k = 0; k < 32; k++) {
            float qv0 = s_qT[k][2 * ty + 0];
            float qv1 = s_qT[k][2 * ty + 1];
            float4 ca = *reinterpret_cast<const float4*>(&s_cT[k][8 * tx]);
            float4 cb = *reinterpret_cast<const float4*>(&s_cT[k][8 * tx + 4]);
            acc[0][0] = fmaf(qv0, ca.x, acc[0][0]); acc[0][1] = fmaf(qv0, ca.y, acc[0][1]);
            acc[0][2] = fmaf(qv0, ca.z, acc[0][2]); acc[0][3] = fmaf(qv0, ca.w, acc[0][3]);
            acc[0][4] = fmaf(qv0, cb.x, acc[0][4]); acc[0][5] = fmaf(qv0, cb.y, acc[0][5]);
            acc[0][6] = fmaf(qv0, cb.z, acc[0][6]); acc[0][7] = fmaf(qv0, cb.w, acc[0][7]);
            acc[1][0] = fmaf(qv1, ca.x, acc[1][0]); acc[1][1] = fmaf(qv1, ca.y, acc[1][1]);
            acc[1][2] = fmaf(qv1, ca.z, acc[1][2]); acc[1][3] = fmaf(qv1, ca.w, acc[1][3]);
            acc[1][4] = fmaf(qv1, cb.x, acc[1][4]); acc[1][5] = fmaf(qv1, cb.y, acc[1][5]);
            acc[1][6] = fmaf(qv1, cb.z, acc[1][6]); acc[1][7] = fmaf(qv1, cb.w, acc[1][7]);
        }
        // dist = sqq + sqc - 2*dot
#pragma unroll
        for (int e = 0; e < 2; e++) {
            float sq = s_sqq[2 * ty + e];
            float4 d0 = make_float4((sq + s_sqc[8 * tx + 0]) - 2.0f * acc[e][0],
                                    (sq + s_sqc[8 * tx + 1]) - 2.0f * acc[e][1],
                                    (sq + s_sqc[8 * tx + 2]) - 2.0f * acc[e][2],
                                    (sq + s_sqc[8 * tx + 3]) - 2.0f * acc[e][3]);
            float4 d1 = make_float4((sq + s_sqc[8 * tx + 4]) - 2.0f * acc[e][4],
                                    (sq + s_sqc[8 * tx + 5]) - 2.0f * acc[e][5],
                                    (sq + s_sqc[8 * tx + 6]) - 2.0f * acc[e][6],
                                    (sq + s_sqc[8 * tx + 7]) - 2.0f * acc[e][7]);
            *reinterpret_cast<float4*>(&s_D[2 * ty + e][8 * tx]) = d0;
            *reinterpret_cast<float4*>(&s_D[2 * ty + e][8 * tx + 4]) = d1;
        }
        __syncthreads();

        // Phase B: 8 lanes per query, disjoint candidate subsets
#pragma unroll
        for (int t2 = 0; t2 < CT / 8; t2++) {
            int c = t2 * 8 + sub;
            knn_insert(s_D[qi][c], base + c, bd, bi);
        }
    }
    __syncthreads();   // done with s_cT / s_D; overlay merge buffers

    // exact 8-lane merge per query
    float* md = reinterpret_cast<float*>(s_cT);
    int*   mi = reinterpret_cast<int*>(s_D);
#pragma unroll
    for (int r = 0; r < KNBR; r++) { md[tid * KNBR + r] = bd[r]; mi[tid * KNBR + r] = bi[r]; }
    __syncwarp();
    int p = 0;
    for (int r = 0; r < KNBR; r++) {
        float cd = (p < KNBR) ? md[tid * KNBR + p] : 3.4e38f;
        int   ci = (p < KNBR) ? mi[tid * KNBR + p] : 0x7FFFFFFF;
        float rd = cd; int ri = ci;
#pragma unroll
        for (int off = 4; off; off >>= 1) {
            float od = __shfl_xor_sync(0xFFFFFFFFu, rd, off);
            int   oi = __shfl_xor_sync(0xFFFFFFFFu, ri, off);
            if (knn_less(od, oi, rd, ri)) { rd = od; ri = oi; }
        }
        if (ci == ri && p < KNBR) p++;   // candidate subsets disjoint per lane
        if (sub == 0) {
            g_pd[1][part][q0 + qi][r] = rd;
            g_pi[1][part][q0 + qi][r] = ri;
        }
    }
}

template <int BR, int P>
__global__ __launch_bounds__(256) void knn_mergeP_kernel() {
    int q = blockIdx.x * 256 + threadIdx.x;
    int p[P];
#pragma unroll
    for (int t = 0; t < P; t++) p[t] = 0;
    for (int r = 0; r < KNBR; r++) {
        float bd = 3.4e38f; int bi = 0x7FFFFFFF, bt = 0;
#pragma unroll
        for (int t = 0; t < P; t++) {
            float d = g_pd[BR][t][q][p[t]];
            int   i = g_pi[BR][t][q][p[t]];
            if (knn_less(d, i, bd, bi)) { bd = d; bi = i; bt = t; }
        }
        p[bt]++;
        g_idx[BR][q * KNBR + r] = bi;
    }
}

// ================= buildS: attrs -> h -> S (bf16 hi/lo), xjmean =================
__global__ __launch_bounds__(128) void buildS_kernel(
    const float* __restrict__ x, const float* __restrict__ pos,
    const float* __restrict__ w1, const float* __restrict__ b1, int br) {
    int n = blockIdx.x;
    int t = threadIdx.x;

    __shared__ int   s_idx[KNBR];
    __shared__ float s_xj[KNBR][INC];
    __shared__ float s_attr[KNBR][3];
    __shared__ float s_h[KNBR][HID];
    __shared__ float s_pn[3];

    const int* idx = g_idx[br];

    if (t < KNBR) s_idx[t] = idx[n * KNBR + t];
    if (t < 3)    s_pn[t] = pos[n * 3 + t];
    __syncthreads();

    for (int v = t; v < KNBR * INC; v += 128)
        s_xj[v / INC][v % INC] = x[(size_t)s_idx[v / INC] * INC + (v % INC)];

    if (t < KNBR) {
        int sj = s_idx[t];
        float cx = pos[sj * 3 + 0] - s_pn[0];
        float cy = pos[sj * 3 + 1] - s_pn[1];
        float cz = pos[sj * 3 + 2] - s_pn[2];
        float rho = sqrtf((cx * cx + cy * cy) + cz * cz);
        float th  = atan2f(cy, cx);
        float ratio = cz / fmaxf(rho, 1e-12f);
        ratio = fminf(1.0f, fmaxf(-1.0f, ratio));
        float ph = acosf(ratio);
        s_attr[t][0] = rho; s_attr[t][1] = th; s_attr[t][2] = ph;
    }
    __syncthreads();

    {
        int c = t;
        float wa = w1[c], wb = w1[HID + c], wc = w1[2 * HID + c], bb = b1[c];
        float hk[KNBR];
#pragma unroll
        for (int k = 0; k < KNBR; k++)
            hk[k] = tanhf(bb + s_attr[k][0] * wa + s_attr[k][1] * wb + s_attr[k][2] * wc);
#pragma unroll
        for (int k = 0; k < KNBR; k++) s_h[k][c] = hk[k];
    }
    __syncthreads();

    int w = t >> 5, lane = t & 31;
    __nv_bfloat16* Sh = g_Sh[br] + (size_t)n * SDIM;
    __nv_bfloat16* Sl = g_Sl[br] + (size_t)n * SDIM;
    for (int j = 0; j < 32; j++) {
        int c = w * 32 + j;
        float s = 0.f;
#pragma unroll
        for (int k = 0; k < KNBR; k++) s = fmaf(s_h[k][c], s_xj[k][lane], s);
        __nv_bfloat16 h = __float2bfloat16(s);
        __nv_bfloat16 l = __float2bfloat16(s - __bfloat162float(h));
        Sh[c * INC + lane] = h;
        Sl[c * INC + lane] = l;
    }
    if (t < INC) {
        float m = 0.f;
#pragma unroll
        for (int k = 0; k < KNBR; k++) m += s_xj[k][t];
        g_xjm[br][n * INC + t] = m * (1.0f / 9.0f);
    }
}

// ================= transpose + split W2 -> Wt hi/lo [o][k] =====================
__global__ __launch_bounds__(256) void transposeW_kernel(
    const float* __restrict__ w2g, const float* __restrict__ w2f) {
    int kt = blockIdx.x, br = blockIdx.y;
    const float* W = br ? w2f : w2g;
    __shared__ float tile[64][65];
    int t = threadIdx.x;
    for (int v = t; v < 64 * 64; v += 256) {
        int kk = v >> 6, o = v & 63;
        tile[kk][o] = W[(size_t)(kt * 64 + kk) * 64 + o];
    }
    __syncthreads();
    for (int v = t; v < 64 * 64; v += 256) {
        int o = v >> 6, kk = v & 63;
        float f = tile[kk][o];
        __nv_bfloat16 h = __float2bfloat16(f);
        __nv_bfloat16 l = __float2bfloat16(f - __bfloat162float(h));
        g_Wth[br][(size_t)o * SDIM + kt * 64 + kk] = h;
        g_Wtl[br][(size_t)o * SDIM + kt * 64 + kk] = l;
    }
}

// ================= GEMM via mma.sync bf16 (hi/lo 3-term) =======================
__device__ __forceinline__ void mma_bf16(float* c, const uint32_t* a, const uint32_t* b) {
    asm volatile(
        "mma.sync.aligned.m16n8k16.row.col.f32.bf16.bf16.f32 "
        "{%0,%1,%2,%3}, {%4,%5,%6,%7}, {%8,%9}, {%0,%1,%2,%3};"
        : "+f"(c[0]), "+f"(c[1]), "+f"(c[2]), "+f"(c[3])
        : "r"(a[0]), "r"(a[1]), "r"(a[2]), "r"(a[3]), "r"(b[0]), "r"(b[1]));
}

#define GSMEM_BYTES ((128 * AST * 2 + 64 * AST * 2) * 2)   // 55296 B

__global__ __launch_bounds__(256) void gemm_kernel() {
    extern __shared__ __align__(16) __nv_bfloat16 sm[];
    __nv_bfloat16* Ah = sm;                  // 128 x AST
    __nv_bfloat16* Al = Ah + 128 * AST;
    __nv_bfloat16* Bh = Al + 128 * AST;      // 64 x AST
    __nv_bfloat16* Bl = Bh + 64 * AST;

    int tid = threadIdx.x, warp = tid >> 5, lane = tid & 31;
    int br = blockIdx.y, kz = blockIdx.z;
    int n0 = blockIdx.x * 128;
    int kbase = kz * KLEN;
    int mw = warp >> 1, nw = warp & 1;       // warp tile: m32 x n32
    int g = lane >> 2, t = lane & 3;

    const __nv_bfloat16* ShG = g_Sh[br];
    const __nv_bfloat16* SlG = g_Sl[br];
    const __nv_bfloat16* WhG = g_Wth[br];
    const __nv_bfloat16* WlG = g_Wtl[br];

    float acc[2][4][4];
#pragma unroll
    for (int mi = 0; mi < 2; mi++)
#pragma unroll
        for (int ni = 0; ni < 4; ni++)
#pragma unroll
            for (int e = 0; e < 4; e++) acc[mi][ni][e] = 0.f;

    for (int c = 0; c < KLEN / KC; c++) {
        int koff = kbase + c * KC;
        __syncthreads();
#pragma unroll
        for (int u = tid; u < 1024; u += 256) {
            int m = u >> 3, j = u & 7;
            size_t s = (size_t)(n0 + m) * SDIM + koff + j * 8;
            *reinterpret_cast<uint4*>(&Ah[m * AST + j * 8]) =
                *reinterpret_cast<const uint4*>(&ShG[s]);
            *reinterpret_cast<uint4*>(&Al[m * AST + j * 8]) =
                *reinterpret_cast<const uint4*>(&SlG[s]);
        }
#pragma unroll
        for (int u = tid; u < 512; u += 256) {
            int o = u >> 3, j = u & 7;
            size_t s = (size_t)o * SDIM + koff + j * 8;
            *reinterpret_cast<uint4*>(&Bh[o * AST + j * 8]) =
                *reinterpret_cast<const uint4*>(&WhG[s]);
            *reinterpret_cast<uint4*>(&Bl[o * AST + j * 8]) =
                *reinterpret_cast<const uint4*>(&WlG[s]);
        }
        __syncthreads();

#pragma unroll
        for (int ks = 0; ks < KC / 16; ks++) {
            int k0 = ks * 16;
            uint32_t ah[2][4], al[2][4], bh[4][2], bl[4][2];
#pragma unroll
            for (int mi = 0; mi < 2; mi++) {
                int r0 = mw * 32 + mi * 16;
                ah[mi][0] = *reinterpret_cast<const uint32_t*>(&Ah[(r0 + g) * AST + k0 + 2 * t]);
                ah[mi][1] = *reinterpret_cast<const uint32_t*>(&Ah[(r0 + g + 8) * AST + k0 + 2 * t]);
                ah[mi][2] = *reinterpret_cast<const uint32_t*>(&Ah[(r0 + g) * AST + k0 + 2 * t + 8]);
                ah[mi][3] = *reinterpret_cast<const uint32_t*>(&Ah[(r0 + g + 8) * AST + k0 + 2 * t + 8]);
                al[mi][0] = *reinterpret_cast<const uint32_t*>(&Al[(r0 + g) * AST + k0 + 2 * t]);
                al[mi][1] = *reinterpret_cast<const uint32_t*>(&Al[(r0 + g + 8) * AST + k0 + 2 * t]);
                al[mi][2] = *reinterpret_cast<const uint32_t*>(&Al[(r0 + g) * AST + k0 + 2 * t + 8]);
                al[mi][3] = *reinterpret_cast<const uint32_t*>(&Al[(r0 + g + 8) * AST + k0 + 2 * t + 8]);
            }
#pragma unroll
            for (int ni = 0; ni < 4; ni++) {
                int o0 = nw * 32 + ni * 8;
                bh[ni][0] = *reinterpret_cast<const uint32_t*>(&Bh[(o0 + g) * AST + k0 + 2 * t]);
                bh[ni][1] = *reinterpret_cast<const uint32_t*>(&Bh[(o0 + g) * AST + k0 + 2 * t + 8]);
                bl[ni][0] = *reinterpret_cast<const uint32_t*>(&Bl[(o0 + g) * AST + k0 + 2 * t]);
                bl[ni][1] = *reinterpret_cast<const uint32_t*>(&Bl[(o0 + g) * AST + k0 + 2 * t + 8]);
            }
#pragma unroll
            for (int mi = 0; mi < 2; mi++)
#pragma unroll
                for (int ni = 0; ni < 4; ni++) {
                    mma_bf16(acc[mi][ni], ah[mi], bh[ni]);
                    mma_bf16(acc[mi][ni], ah[mi], bl[ni]);
                    mma_bf16(acc[mi][ni], al[mi], bh[ni]);
                }
        }
    }

    float* P = &g_part[br][kz][0][0];
#pragma unroll
    for (int mi = 0; mi < 2; mi++) {
        int r0 = mw * 32 + mi * 16;
#pragma unroll
        for (int ni = 0; ni < 4; ni++) {
            int col = nw * 32 + ni * 8 + 2 * t;
            float2 v01 = make_float2(acc[mi][ni][0], acc[mi][ni][1]);
            float2 v23 = make_float2(acc[mi][ni][2], acc[mi][ni][3]);
            *reinterpret_cast<float2*>(&P[(size_t)(n0 + r0 + g) * OUTC + col]) = v01;
            *reinterpret_cast<float2*>(&P[(size_t)(n0 + r0 + g + 8) * OUTC + col]) = v23;
        }
    }
}

// ================= combine: out = 0.5*((sum parts)/9 + xm@b2 both) =============
__global__ __launch_bounds__(256) void combine_kernel(
    const float* __restrict__ b2g, const float* __restrict__ b2f,
    float* __restrict__ out) {
    __shared__ float s_b2[2][INC * OUTC];
    __shared__ float s_xm[2][4][INC];

    int tid = threadIdx.x;
    int nl = tid >> 6, o = tid & 63;
    int n = blockIdx.x * 4 + nl;

    for (int v = tid; v < INC * OUTC; v += 256) {
        s_b2[0][v] = b2g[v];
        s_b2[1][v] = b2f[v];
    }
    {
        int br = tid >> 7, nn = (tid >> 5) & 3, i = tid & 31;
        s_xm[br][nn][i] = g_xjm[br][(size_t)(blockIdx.x * 4 + nn) * INC + i];
    }
    __syncthreads();

    float val = 0.f;
#pragma unroll
    for (int br = 0; br < 2; br++)
#pragma unroll
        for (int kzi = 0; kzi < KSPL; kzi++)
            val += g_part[br][kzi][n][o];
    val *= (1.0f / 9.0f);
#pragma unroll
    for (int br = 0; br < 2; br++)
#pragma unroll
        for (int i = 0; i < INC; i++)
            val = fmaf(s_xm[br][nl][i], s_b2[br][i * OUTC + o], val);
    out[(size_t)n * OUTC + o] = 0.5f * val;
}

// ---------------- launch -------------------------------------------------------
extern "C" void kernel_launch(void* const* d_in, const int* in_sizes, int n_in,
                              void* d_out, int out_size) {
    const float* x   = (const float*)d_in[0];
    const float* pos = (const float*)d_in[1];
    const float* w1g = (const float*)d_in[2];
    const float* b1g = (const float*)d_in[3];
    const float* w2g = (const float*)d_in[4];
    const float* b2g = (const float*)d_in[5];
    const float* w1f = (const float*)d_in[6];
    const float* b1f = (const float*)d_in[7];
    const float* w2f = (const float*)d_in[8];
    const float* b2f = (const float*)d_in[9];
    float* out = (float*)d_out;

    cudaFuncSetAttribute(gemm_kernel, cudaFuncAttributeMaxDynamicSharedMemorySize,
                         GSMEM_BYTES);

    knn_pos_kernel<<<dim3(NND / 8, 2), 256>>>(pos);                   // 0
    knn_mergeP_kernel<0, 2><<<NND / 256, 256>>>();                    // 1
    buildS_kernel<<<NND, 128>>>(x, pos, w1g, b1g, 0);                 // 2
    knn_feat_kernel<<<dim3(NND / 32, 8), 256>>>(x);                   // 3  <- profiled
    knn_mergeP_kernel<1, 8><<<NND / 256, 256>>>();                    // 4
    buildS_kernel<<<NND, 128>>>(x, pos, w1f, b1f, 1);                 // 5
    transposeW_kernel<<<dim3(SDIM / 64, 2), 256>>>(w2g, w2f);         // 6
    gemm_kernel<<<dim3(NND / 128, 2, KSPL), 256, GSMEM_BYTES>>>();    // 7
    combine_kernel<<<NND / 4, 256>>>(b2g, b2f, out);                  // 8
}